// round 4
// baseline (speedup 1.0000x reference)
#include <cuda_runtime.h>
#include <cuda_bf16.h>
#include <math.h>

#define NN 6000
#define EE 100000
typedef unsigned long long ull;

// ---------------- scratch ----------------
__device__ float g_x[NN * 64];
__device__ float g_y[NN * 64];
__device__ float g_hr[2 * NN * 32];     // layer0 relation rows
__device__ float g_W1[32 * 128];        // [I, 2*O] per layer
__device__ float g_W2[64 * 128];
__device__ float g_W3[64 * 64];
__device__ int   g_cnt[2 * NN];
__device__ float g_rinv[2 * NN];
__device__ int   g_deg[NN];
__device__ int   g_offs[NN + 1];
__device__ int   g_cur[NN];
__device__ int   g_csr[EE];             // src | (rel<<16)
__device__ float g_h[NN * 512];
__device__ float g_asv[NN], g_adv[NN];
__device__ float g_o512[NN * 512];
__device__ float g_A[NN * 128], g_B[NN * 128];

// ---------------- f32x2 helpers ----------------
__device__ __forceinline__ void ffma2(ull& d, ull a, ull b) {
    asm("fma.rn.f32x2 %0, %1, %2, %0;" : "+l"(d) : "l"(a), "l"(b));
}
__device__ __forceinline__ ull pack2(float a) {
    ull p;
    asm("mov.b64 %0, {%1, %1};" : "=l"(p) : "f"(a));
    return p;
}

// ---------------- CSR build ----------------
__global__ void zero_k() {
    int i = blockIdx.x * blockDim.x + threadIdx.x;
    if (i < 2 * NN) g_cnt[i] = 0;
    if (i < NN) { g_deg[i] = 0; g_cur[i] = 0; }
}
__global__ void count_k(const int* __restrict__ et, const int* __restrict__ dst) {
    int e = blockIdx.x * blockDim.x + threadIdx.x;
    if (e < EE) {
        int d = dst[e];
        atomicAdd(&g_deg[d], 1);
        atomicAdd(&g_cnt[et[e] * NN + d], 1);
    }
}
__global__ void scan_k() {     // 1 block, 1024 threads: exclusive scan of deg + rinv
    __shared__ int ws[32];
    int t = threadIdx.x;
    for (int i = t; i < 2 * NN; i += 1024)
        g_rinv[i] = 1.0f / fmaxf((float)g_cnt[i], 1.0f);
    int base = t * 6;
    int loc[6]; int s = 0;
#pragma unroll
    for (int j = 0; j < 6; j++) {
        int idx = base + j; loc[j] = s;
        s += (idx < NN) ? g_deg[idx] : 0;
    }
    int lane = t & 31, w = t >> 5;
    int v = s;
#pragma unroll
    for (int off = 1; off < 32; off <<= 1) {
        int nv = __shfl_up_sync(0xffffffffu, v, off);
        if (lane >= off) v += nv;
    }
    if (lane == 31) ws[w] = v;
    __syncthreads();
    if (w == 0) {
        int x = ws[lane];
#pragma unroll
        for (int off = 1; off < 32; off <<= 1) {
            int nv = __shfl_up_sync(0xffffffffu, x, off);
            if (lane >= off) x += nv;
        }
        ws[lane] = x;
    }
    __syncthreads();
    int excl = v - s + (w ? ws[w - 1] : 0);
#pragma unroll
    for (int j = 0; j < 6; j++) {
        int idx = base + j;
        if (idx < NN) g_offs[idx] = excl + loc[j];
    }
    if (t == 1023) g_offs[NN] = excl + s;
}
__global__ void scatter_k(const int* __restrict__ src, const int* __restrict__ dst,
                          const int* __restrict__ et) {
    int e = blockIdx.x * blockDim.x + threadIdx.x;
    if (e >= EE) return;
    int d = dst[e];
    int pos = g_offs[d] + atomicAdd(&g_cur[d], 1);
    g_csr[pos] = src[e] | (et[e] << 16);
}

// ---------------- precompute: l0_hr + Wcat for layers 1..3 ----------------
__device__ __forceinline__ void wcat_one(float* W, const float* basis, const float* comp,
                                         int I, int O, int i) {
    int r = i / (I * O), io = i % (I * O);
    float acc = 0.f;
#pragma unroll
    for (int b = 0; b < 4; b++) acc += comp[r * 4 + b] * basis[b * I * O + io];
    W[(io / O) * 2 * O + r * O + (io % O)] = acc;
}
#define R0 (2 * NN * 32)
__global__ void precomp_k(const float* __restrict__ basis0, const float* __restrict__ comp0,
                          const float* __restrict__ b1s, const float* __restrict__ c1,
                          const float* __restrict__ b2s, const float* __restrict__ c2,
                          const float* __restrict__ b3s, const float* __restrict__ c3) {
    int i = blockIdx.x * blockDim.x + threadIdx.x;
    if (i < R0) {
        int r = i / (NN * 32), idx = i % (NN * 32);
        float acc = 0.f;
#pragma unroll
        for (int b = 0; b < 4; b++) acc += comp0[r * 4 + b] * basis0[b * NN * 32 + idx];
        g_hr[r * NN * 32 + idx] = acc;
    } else if (i < R0 + 4096) {
        wcat_one(g_W1, b1s, c1, 32, 64, i - R0);
    } else if (i < R0 + 4096 + 8192) {
        wcat_one(g_W2, b2s, c2, 64, 64, i - R0 - 4096);
    } else if (i < R0 + 4096 + 8192 + 4096) {
        wcat_one(g_W3, b3s, c3, 64, 32, i - R0 - 4096 - 8192);
    }
}

// ---------------- layer 0 (identity shortcut): gather + root + tanh ----------------
__global__ void l0_agg_k(const float* __restrict__ root0, const float* __restrict__ rbias0) {
    int n = blockIdx.x * 4 + (threadIdx.x >> 5);
    int lane = threadIdx.x & 31;
    if (n >= NN) return;
    int o = g_offs[n], e2 = g_offs[n + 1];
    float a0 = 0.f, a1 = 0.f;
    for (int p = o; p < e2; p++) {
        int pk = g_csr[p];
        float v = g_hr[(pk >> 16) * NN * 32 + (pk & 0xffff) * 32 + lane];
        if (pk & 0x10000) a1 += v; else a0 += v;
    }
    float out = root0[n * 32 + lane] + rbias0[lane] + a0 * g_rinv[n] + a1 * g_rinv[NN + n];
    g_x[n * 32 + lane] = tanhf(out);
}

// ---------------- fused RGCN layer: aggregate + GEMM + tanh ----------------
// blockDim (64,4); 4 nodes per block.
__global__ void layer_k(const float* __restrict__ root, const float* __restrict__ rbias,
                        const float* __restrict__ Wcat, int I, int O,
                        const float* __restrict__ xin, float* __restrict__ xout) {
    __shared__ float xs[4][64], a0s[4][64], a1s[4][64];
    int ty = threadIdx.y, tx = threadIdx.x;
    int n = blockIdx.x * 4 + ty;
    if (tx < I) {
        int o = g_offs[n], e2 = g_offs[n + 1];
        float a0 = 0.f, a1 = 0.f;
        for (int p = o; p < e2; p++) {
            int pk = g_csr[p];
            float v = xin[(pk & 0xffff) * I + tx];
            if (pk & 0x10000) a1 += v; else a0 += v;
        }
        xs[ty][tx] = xin[n * I + tx];
        a0s[ty][tx] = a0 * g_rinv[n];
        a1s[ty][tx] = a1 * g_rinv[NN + n];
    }
    __syncthreads();
    if (tx < O) {
        float acc = rbias[tx];
#pragma unroll 8
        for (int i = 0; i < I; i++) {
            acc += xs[ty][i] * root[i * O + tx];
            acc += a0s[ty][i] * Wcat[i * 2 * O + tx];
            acc += a1s[ty][i] * Wcat[i * 2 * O + O + tx];
        }
        xout[n * O + tx] = tanhf(acc);
    }
}

// ---------------- GAT ----------------
__global__ void gat_h_k(const float* __restrict__ gw, const float* __restrict__ asrc,
                        const float* __restrict__ adst) {
    __shared__ float xs[32];
    __shared__ float reda[8], redd[8];
    int n = blockIdx.x, tid = threadIdx.x;
    if (tid < 32) xs[tid] = g_y[n * 32 + tid];
    __syncthreads();
    float a0 = 0.f, a1 = 0.f;
    int c0 = tid, c1 = tid + 256;
#pragma unroll 8
    for (int i = 0; i < 32; i++) {
        float xv = xs[i];
        a0 += xv * gw[i * 512 + c0];
        a1 += xv * gw[i * 512 + c1];
    }
    g_h[n * 512 + c0] = a0;
    g_h[n * 512 + c1] = a1;
    float pa = a0 * asrc[c0] + a1 * asrc[c1];
    float pd = a0 * adst[c0] + a1 * adst[c1];
#pragma unroll
    for (int off = 16; off; off >>= 1) {
        pa += __shfl_down_sync(0xffffffffu, pa, off);
        pd += __shfl_down_sync(0xffffffffu, pd, off);
    }
    if ((tid & 31) == 0) { reda[tid >> 5] = pa; redd[tid >> 5] = pd; }
    __syncthreads();
    if (tid == 0) {
        float sa = 0.f, sd = 0.f;
#pragma unroll
        for (int w = 0; w < 8; w++) { sa += reda[w]; sd += redd[w]; }
        g_asv[n] = sa;
        g_adv[n] = sd;
    }
}

__global__ void gat_node_k() {
    __shared__ float sal[1024];
    __shared__ int ssrc[1024];
    __shared__ float red[128];
    int n = blockIdx.x, tid = threadIdx.x;
    int o = g_offs[n];
    int deg = g_offs[n + 1] - o;
    if (deg > 1024) deg = 1024;
    float advn = g_adv[n];
    float lm = -1e30f;
    for (int p = tid; p < deg; p += 128) {
        int s = g_csr[o + p] & 0xffff;
        ssrc[p] = s;
        float a = g_asv[s] + advn;
        a = a > 0.f ? a : 0.2f * a;
        sal[p] = a;
        lm = fmaxf(lm, a);
    }
    float als = g_asv[n] + advn;
    als = als > 0.f ? als : 0.2f * als;
    lm = fmaxf(lm, als);
    red[tid] = lm; __syncthreads();
    for (int st = 64; st; st >>= 1) {
        if (tid < st) red[tid] = fmaxf(red[tid], red[tid + st]);
        __syncthreads();
    }
    float m = red[0];
    __syncthreads();
    float ls = 0.f;
    for (int p = tid; p < deg; p += 128) {
        float ex = expf(sal[p] - m);
        sal[p] = ex;
        ls += ex;
    }
    float exs = expf(als - m);
    if (tid == 0) ls += exs;
    red[tid] = ls; __syncthreads();
    for (int st = 64; st; st >>= 1) {
        if (tid < st) red[tid] += red[tid + st];
        __syncthreads();
    }
    float invden = 1.f / fmaxf(red[0], 1e-16f);
    // weighted sum (unnormalized), thread owns 4 cols
    float4 hv = ((const float4*)&g_h[n * 512])[tid];
    float4 acc;
    acc.x = exs * hv.x; acc.y = exs * hv.y; acc.z = exs * hv.z; acc.w = exs * hv.w;
#pragma unroll 2
    for (int p = 0; p < deg; p++) {
        int s = ssrc[p];
        float c = sal[p];
        float4 h4 = ((const float4*)&g_h[s * 512])[tid];
        acc.x += c * h4.x; acc.y += c * h4.y; acc.z += c * h4.z; acc.w += c * h4.w;
    }
    acc.x *= invden; acc.y *= invden; acc.z *= invden; acc.w *= invden;
    ((float4*)&g_o512[n * 512])[tid] = acc;
}

// ---------------- AB GEMM with f32x2: out[N,256] = relu(o512+gbias) @ Wab ----------------
// tile 64(M) x 128(N), BK=16, 256 threads, per-thread 4m x 8n (4 f32x2 pairs)
__global__ void ab_gemm_k(const float* __restrict__ w1, const float* __restrict__ b1,
                          const float* __restrict__ gbias) {
    __shared__ float As[16][68];
    __shared__ float Bs[16][128];
    int tid = threadIdx.x;
    int bm = blockIdx.x * 64;
    int by = blockIdx.y;           // 0: A-half (w1 rows 0..511), 1: B-half (512..1023)
    int ty = tid >> 4, tx = tid & 15;
    ull acc[4][4] = {};
    for (int k0 = 0; k0 < 512; k0 += 16) {
        // load A: thread -> m=tid&63, kk group=tid>>6 (4 k's)
        {
            int mm = tid & 63, kg = tid >> 6;
            int gm = bm + mm;
            float4 v = make_float4(0.f, 0.f, 0.f, 0.f);
            if (gm < NN) v = *(const float4*)&g_o512[gm * 512 + k0 + kg * 4];
            const float4 gb = *(const float4*)&gbias[k0 + kg * 4];
            As[kg * 4 + 0][mm] = fmaxf(v.x + gb.x, 0.f);
            As[kg * 4 + 1][mm] = fmaxf(v.y + gb.y, 0.f);
            As[kg * 4 + 2][mm] = fmaxf(v.z + gb.z, 0.f);
            As[kg * 4 + 3][mm] = fmaxf(v.w + gb.w, 0.f);
        }
        // load B: 16x128; row = k0+kk + by*512
        {
            int id = tid * 4;          // covers 1024 of 2048
#pragma unroll
            for (int rep = 0; rep < 2; rep++, id += 1024) {
                int kk = id >> 7, col = id & 127;
                float4 v = *(const float4*)&w1[(k0 + kk + by * 512) * 128 + col];
                *(float4*)&Bs[kk][col] = v;
            }
        }
        __syncthreads();
#pragma unroll
        for (int kk = 0; kk < 16; kk++) {
            float4 av = *(const float4*)&As[kk][ty * 4];
            ull ap[4];
            ap[0] = pack2(av.x); ap[1] = pack2(av.y);
            ap[2] = pack2(av.z); ap[3] = pack2(av.w);
            const ull* bp = (const ull*)&Bs[kk][tx * 8];
            ull b0 = bp[0], bb1 = bp[1], b2 = bp[2], b3 = bp[3];
#pragma unroll
            for (int i = 0; i < 4; i++) {
                ffma2(acc[i][0], ap[i], b0);
                ffma2(acc[i][1], ap[i], bb1);
                ffma2(acc[i][2], ap[i], b2);
                ffma2(acc[i][3], ap[i], b3);
            }
        }
        __syncthreads();
    }
    float* dstbuf = by == 0 ? g_A : g_B;
#pragma unroll
    for (int i = 0; i < 4; i++) {
        int gm = bm + ty * 4 + i;
        if (gm >= NN) continue;
#pragma unroll
        for (int j = 0; j < 4; j++) {
            int c = tx * 8 + 2 * j;
            float lo = __uint_as_float((unsigned)(acc[i][j] & 0xffffffffu));
            float hi = __uint_as_float((unsigned)(acc[i][j] >> 32));
            if (by == 0) { lo += b1[c]; hi += b1[c + 1]; }
            float2 st = make_float2(lo, hi);
            *(float2*)&dstbuf[gm * 128 + c] = st;
        }
    }
}

__global__ void final_k(const int* __restrict__ src, const int* __restrict__ dst,
                        const float* __restrict__ w2, const float* __restrict__ b2,
                        float* __restrict__ out) {
    int e = blockIdx.x * 4 + (threadIdx.x >> 5);
    int lane = threadIdx.x & 31;
    if (e >= EE) return;
    int s = src[e], d = dst[e];
    float4 a = *(const float4*)&g_A[s * 128 + lane * 4];
    float4 b = *(const float4*)&g_B[d * 128 + lane * 4];
    float4 w = *(const float4*)&w2[lane * 4];
    float sum = fmaxf(a.x + b.x, 0.f) * w.x + fmaxf(a.y + b.y, 0.f) * w.y +
                fmaxf(a.z + b.z, 0.f) * w.z + fmaxf(a.w + b.w, 0.f) * w.w;
#pragma unroll
    for (int off = 16; off; off >>= 1) sum += __shfl_down_sync(0xffffffffu, sum, off);
    if (lane == 0) out[e] = 1.f / (1.f + expf(-(sum + b2[0])));
}

// ---------------- host ----------------
extern "C" void kernel_launch(void* const* d_in, const int* in_sizes, int n_in,
                              void* d_out, int out_size) {
    int b = (in_sizes[0] == 2 * EE) ? 2 : 0;
    const int* eidx = (const int*)(b ? d_in[0] : d_in[24]);
    const int* etype = (const int*)(b ? d_in[1] : d_in[25]);
    const int* src = eidx;
    const int* dst = eidx + EE;
    auto F = [&](int i) { return (const float*)d_in[i]; };

    zero_k<<<(2 * NN + 255) / 256, 256>>>();
    count_k<<<(EE + 255) / 256, 256>>>(etype, dst);
    scan_k<<<1, 1024>>>();
    scatter_k<<<(EE + 255) / 256, 256>>>(src, dst, etype);

    int ptot = R0 + 4096 + 8192 + 4096;
    precomp_k<<<(ptot + 255) / 256, 256>>>(F(b + 0), F(b + 1),
                                           F(b + 4), F(b + 5),
                                           F(b + 8), F(b + 9),
                                           F(b + 12), F(b + 13));
    l0_agg_k<<<NN / 4, 128>>>(F(b + 2), F(b + 3));

    dim3 blk(64, 4);
    layer_k<<<NN / 4, blk>>>(F(b + 6),  F(b + 7),  g_W1, 32, 64, g_x, g_y);
    layer_k<<<NN / 4, blk>>>(F(b + 10), F(b + 11), g_W2, 64, 64, g_y, g_x);
    layer_k<<<NN / 4, blk>>>(F(b + 14), F(b + 15), g_W3, 64, 32, g_x, g_y);

    gat_h_k<<<NN, 256>>>(F(b + 16), F(b + 17), F(b + 18));
    gat_node_k<<<NN, 128>>>();

    dim3 abgrid((NN + 63) / 64, 2);
    ab_gemm_k<<<abgrid, 256>>>(F(b + 20), F(b + 21), F(b + 19));
    final_k<<<(EE + 3) / 4, 128>>>(src, dst, F(b + 22), F(b + 23), (float*)d_out);
}

// round 5
// speedup vs baseline: 1.0307x; 1.0307x over previous
#include <cuda_runtime.h>
#include <cuda_bf16.h>
#include <math.h>

#define NN 6000
#define EE 100000

// ---------------- scratch ----------------
__device__ float g_x[NN * 64];
__device__ float g_y[NN * 64];
__device__ float g_hr[2 * NN * 32];
__device__ float g_s[2 * NN * 64];
__device__ float g_W1[32 * 128];
__device__ float g_W2[64 * 128];
__device__ float g_W3[64 * 64];
__device__ int   g_cnt[2 * NN];
__device__ float g_rinv[2 * NN];
__device__ int   g_deg[NN];
__device__ int   g_offs[NN + 1];
__device__ int   g_cur[NN];
__device__ int   g_csr[EE];
__device__ float g_h[NN * 512];
__device__ float g_asv[NN], g_adv[NN];
__device__ float g_o512[NN * 512];
__device__ float g_A[NN * 128], g_B[NN * 128];

// ---------------- CSR build ----------------
__global__ void zero_k() {
    int i = blockIdx.x * blockDim.x + threadIdx.x;
    if (i < 2 * NN) g_cnt[i] = 0;
    if (i < NN) { g_deg[i] = 0; g_cur[i] = 0; }
}
__global__ void count_k(const int* __restrict__ et, const int* __restrict__ dst) {
    int e = blockIdx.x * blockDim.x + threadIdx.x;
    if (e < EE) {
        int d = dst[e];
        atomicAdd(&g_deg[d], 1);
        atomicAdd(&g_cnt[et[e] * NN + d], 1);
    }
}
__global__ void scan_k() {
    __shared__ int ws[32];
    int t = threadIdx.x;
    for (int i = t; i < 2 * NN; i += 1024)
        g_rinv[i] = 1.0f / fmaxf((float)g_cnt[i], 1.0f);
    int base = t * 6;
    int loc[6]; int s = 0;
#pragma unroll
    for (int j = 0; j < 6; j++) {
        int idx = base + j; loc[j] = s;
        s += (idx < NN) ? g_deg[idx] : 0;
    }
    int lane = t & 31, w = t >> 5;
    int v = s;
#pragma unroll
    for (int off = 1; off < 32; off <<= 1) {
        int nv = __shfl_up_sync(0xffffffffu, v, off);
        if (lane >= off) v += nv;
    }
    if (lane == 31) ws[w] = v;
    __syncthreads();
    if (w == 0) {
        int x = ws[lane];
#pragma unroll
        for (int off = 1; off < 32; off <<= 1) {
            int nv = __shfl_up_sync(0xffffffffu, x, off);
            if (lane >= off) x += nv;
        }
        ws[lane] = x;
    }
    __syncthreads();
    int excl = v - s + (w ? ws[w - 1] : 0);
#pragma unroll
    for (int j = 0; j < 6; j++) {
        int idx = base + j;
        if (idx < NN) g_offs[idx] = excl + loc[j];
    }
    if (t == 1023) g_offs[NN] = excl + s;
}
__global__ void scatter_k(const int* __restrict__ src, const int* __restrict__ dst,
                          const int* __restrict__ et) {
    int e = blockIdx.x * blockDim.x + threadIdx.x;
    if (e >= EE) return;
    int d = dst[e];
    int pos = g_offs[d] + atomicAdd(&g_cur[d], 1);
    g_csr[pos] = src[e] | (et[e] << 16);
}

// ---------------- precompute: l0_hr + Wcat for layers 1..3 ----------------
__device__ __forceinline__ void wcat_one(float* W, const float* basis, const float* comp,
                                         int I, int O, int i) {
    int r = i / (I * O), io = i % (I * O);
    float acc = 0.f;
#pragma unroll
    for (int b = 0; b < 4; b++) acc += comp[r * 4 + b] * basis[b * I * O + io];
    W[(io / O) * 2 * O + r * O + (io % O)] = acc;
}
#define R0 (2 * NN * 32)
__global__ void precomp_k(const float* __restrict__ basis0, const float* __restrict__ comp0,
                          const float* __restrict__ b1s, const float* __restrict__ c1,
                          const float* __restrict__ b2s, const float* __restrict__ c2,
                          const float* __restrict__ b3s, const float* __restrict__ c3) {
    int i = blockIdx.x * blockDim.x + threadIdx.x;
    if (i < R0) {
        int r = i / (NN * 32), idx = i % (NN * 32);
        float acc = 0.f;
#pragma unroll
        for (int b = 0; b < 4; b++) acc += comp0[r * 4 + b] * basis0[b * NN * 32 + idx];
        g_hr[r * NN * 32 + idx] = acc;
    } else if (i < R0 + 4096) {
        wcat_one(g_W1, b1s, c1, 32, 64, i - R0);
    } else if (i < R0 + 4096 + 8192) {
        wcat_one(g_W2, b2s, c2, 64, 64, i - R0 - 4096);
    } else if (i < R0 + 4096 + 8192 + 4096) {
        wcat_one(g_W3, b3s, c3, 64, 32, i - R0 - 4096 - 8192);
    }
}

// ---------------- layer 0 ----------------
__global__ void l0_agg_k(const float* __restrict__ root0, const float* __restrict__ rbias0) {
    int n = blockIdx.x * 4 + (threadIdx.x >> 5);
    int lane = threadIdx.x & 31;
    if (n >= NN) return;
    int o = g_offs[n], e2 = g_offs[n + 1];
    float a0 = 0.f, a1 = 0.f;
    for (int p = o; p < e2; p++) {
        int pk = g_csr[p];
        float v = g_hr[(pk >> 16) * NN * 32 + (pk & 0xffff) * 32 + lane];
        if (pk & 0x10000) a1 += v; else a0 += v;
    }
    float out = root0[n * 32 + lane] + rbias0[lane] + a0 * g_rinv[n] + a1 * g_rinv[NN + n];
    g_x[n * 32 + lane] = tanhf(out);
}

// ---------------- RGCN layers 1..3 (R2-proven split) ----------------
__global__ void aggx_k(int I, const float* __restrict__ xin) {
    int n = blockIdx.x * 4 + (threadIdx.x >> 5);
    int lane = threadIdx.x & 31;
    if (n >= NN) return;
    int o = g_offs[n], e2 = g_offs[n + 1];
    float a00 = 0.f, a01 = 0.f, a10 = 0.f, a11 = 0.f;
    for (int p = o; p < e2; p++) {
        int pk = g_csr[p];
        int s = pk & 0xffff;
        float v0 = xin[s * I + lane];
        float v1 = (I == 64) ? xin[s * I + lane + 32] : 0.f;
        if (pk & 0x10000) { a10 += v0; a11 += v1; }
        else              { a00 += v0; a01 += v1; }
    }
    float r0 = g_rinv[n], r1 = g_rinv[NN + n];
    g_s[n * I + lane] = a00 * r0;
    g_s[NN * I + n * I + lane] = a10 * r1;
    if (I == 64) {
        g_s[n * I + lane + 32] = a01 * r0;
        g_s[NN * I + n * I + lane + 32] = a11 * r1;
    }
}
__global__ void rgcn_gemm2_k(const float* __restrict__ root, const float* __restrict__ rbias,
                             const float* __restrict__ Wcat, int I, int O,
                             const float* __restrict__ xin, float* __restrict__ xout) {
    __shared__ float xs[4][64], a0s[4][64], a1s[4][64];
    int ty = threadIdx.y, tx = threadIdx.x;
    int n = blockIdx.x * 4 + ty;
    for (int i = tx; i < I; i += O) {
        xs[ty][i]  = xin[n * I + i];
        a0s[ty][i] = g_s[n * I + i];
        a1s[ty][i] = g_s[NN * I + n * I + i];
    }
    __syncthreads();
    float acc = rbias[tx];
#pragma unroll 8
    for (int i = 0; i < I; i++) {
        acc += xs[ty][i] * root[i * O + tx];
        acc += a0s[ty][i] * Wcat[i * 2 * O + tx];
        acc += a1s[ty][i] * Wcat[i * 2 * O + O + tx];
    }
    xout[n * O + tx] = tanhf(acc);
}

// ---------------- GAT ----------------
__global__ void gat_h_k(const float* __restrict__ gw, const float* __restrict__ asrc,
                        const float* __restrict__ adst) {
    __shared__ float xs[32];
    __shared__ float reda[8], redd[8];
    int n = blockIdx.x, tid = threadIdx.x;
    if (tid < 32) xs[tid] = g_y[n * 32 + tid];
    __syncthreads();
    float a0 = 0.f, a1 = 0.f;
    int c0 = tid, c1 = tid + 256;
#pragma unroll 8
    for (int i = 0; i < 32; i++) {
        float xv = xs[i];
        a0 += xv * gw[i * 512 + c0];
        a1 += xv * gw[i * 512 + c1];
    }
    g_h[n * 512 + c0] = a0;
    g_h[n * 512 + c1] = a1;
    float pa = a0 * asrc[c0] + a1 * asrc[c1];
    float pd = a0 * adst[c0] + a1 * adst[c1];
#pragma unroll
    for (int off = 16; off; off >>= 1) {
        pa += __shfl_down_sync(0xffffffffu, pa, off);
        pd += __shfl_down_sync(0xffffffffu, pd, off);
    }
    if ((tid & 31) == 0) { reda[tid >> 5] = pa; redd[tid >> 5] = pd; }
    __syncthreads();
    if (tid == 0) {
        float sa = 0.f, sd = 0.f;
#pragma unroll
        for (int w = 0; w < 8; w++) { sa += reda[w]; sd += redd[w]; }
        g_asv[n] = sa;
        g_adv[n] = sd;
    }
}

// block(128) per node: softmax + weighted sum (R2 numerics order, + ssrc smem cache)
__global__ void gat_node_k() {
    __shared__ float sal[1024];
    __shared__ int ssrc[1024];
    __shared__ float red[128];
    int n = blockIdx.x, tid = threadIdx.x;
    int o = g_offs[n];
    int deg = g_offs[n + 1] - o;
    if (deg > 1024) deg = 1024;
    float advn = g_adv[n];
    float lm = -1e30f;
    for (int p = tid; p < deg; p += 128) {
        int s = g_csr[o + p] & 0xffff;
        ssrc[p] = s;
        float a = g_asv[s] + advn;
        a = a > 0.f ? a : 0.2f * a;
        sal[p] = a;
        lm = fmaxf(lm, a);
    }
    float als = g_asv[n] + advn;
    als = als > 0.f ? als : 0.2f * als;
    lm = fmaxf(lm, als);
    red[tid] = lm; __syncthreads();
    for (int st = 64; st; st >>= 1) {
        if (tid < st) red[tid] = fmaxf(red[tid], red[tid + st]);
        __syncthreads();
    }
    float m = red[0];
    __syncthreads();
    float ls = 0.f;
    for (int p = tid; p < deg; p += 128) {
        float ex = expf(sal[p] - m);
        sal[p] = ex;
        ls += ex;
    }
    float exs = expf(als - m);
    if (tid == 0) ls += exs;
    red[tid] = ls; __syncthreads();
    for (int st = 64; st; st >>= 1) {
        if (tid < st) red[tid] += red[tid + st];
        __syncthreads();
    }
    float invden = 1.f / fmaxf(red[0], 1e-16f);
    float cs = exs * invden;
    float4 hv = ((const float4*)&g_h[n * 512])[tid];
    float4 acc;
    acc.x = cs * hv.x; acc.y = cs * hv.y; acc.z = cs * hv.z; acc.w = cs * hv.w;
    for (int p = 0; p < deg; p++) {
        int s = ssrc[p];
        float c = sal[p] * invden;
        float4 h4 = ((const float4*)&g_h[s * 512])[tid];
        acc.x += c * h4.x; acc.y += c * h4.y; acc.z += c * h4.z; acc.w += c * h4.w;
    }
    ((float4*)&g_o512[n * 512])[tid] = acc;
}

// ---------------- AB GEMM (scalar, 64M x 128N tile, BK=16, 4x8/thread) ----------------
__global__ void ab_gemm_k(const float* __restrict__ w1, const float* __restrict__ b1,
                          const float* __restrict__ gbias) {
    __shared__ float As[16][68];
    __shared__ float Bs[16][128];
    int tid = threadIdx.x;
    int bm = blockIdx.x * 64;
    int by = blockIdx.y;           // 0 -> g_A half (w1 rows 0..511), 1 -> g_B half
    int ty = tid >> 4, tx = tid & 15;
    float acc[4][8] = {};
    for (int k0 = 0; k0 < 512; k0 += 16) {
        {
            int mm = tid & 63, kg = tid >> 6;
            int gm = bm + mm;
            float4 v = make_float4(0.f, 0.f, 0.f, 0.f);
            if (gm < NN) v = *(const float4*)&g_o512[gm * 512 + k0 + kg * 4];
            const float4 gb = *(const float4*)&gbias[k0 + kg * 4];
            As[kg * 4 + 0][mm] = fmaxf(v.x + gb.x, 0.f);
            As[kg * 4 + 1][mm] = fmaxf(v.y + gb.y, 0.f);
            As[kg * 4 + 2][mm] = fmaxf(v.z + gb.z, 0.f);
            As[kg * 4 + 3][mm] = fmaxf(v.w + gb.w, 0.f);
        }
        {
            int id = tid * 4;
#pragma unroll
            for (int rep = 0; rep < 2; rep++, id += 1024) {
                int kk = id >> 7, col = id & 127;
                float4 v = *(const float4*)&w1[(k0 + kk + by * 512) * 128 + col];
                *(float4*)&Bs[kk][col] = v;
            }
        }
        __syncthreads();
#pragma unroll
        for (int kk = 0; kk < 16; kk++) {
            float a[4], bb[8];
#pragma unroll
            for (int i = 0; i < 4; i++) a[i] = As[kk][ty * 4 + i];
#pragma unroll
            for (int j = 0; j < 8; j++) bb[j] = Bs[kk][tx * 8 + j];
#pragma unroll
            for (int i = 0; i < 4; i++)
#pragma unroll
                for (int j = 0; j < 8; j++) acc[i][j] += a[i] * bb[j];
        }
        __syncthreads();
    }
    float* dstbuf = by == 0 ? g_A : g_B;
#pragma unroll
    for (int i = 0; i < 4; i++) {
        int gm = bm + ty * 4 + i;
        if (gm >= NN) continue;
#pragma unroll
        for (int j = 0; j < 8; j++) {
            int c = tx * 8 + j;
            float v = acc[i][j];
            if (by == 0) v += b1[c];
            dstbuf[gm * 128 + c] = v;
        }
    }
}

__global__ void final_k(const int* __restrict__ src, const int* __restrict__ dst,
                        const float* __restrict__ w2, const float* __restrict__ b2,
                        float* __restrict__ out) {
    int e = blockIdx.x * 4 + (threadIdx.x >> 5);
    int lane = threadIdx.x & 31;
    if (e >= EE) return;
    int s = src[e], d = dst[e];
    float4 a = *(const float4*)&g_A[s * 128 + lane * 4];
    float4 b = *(const float4*)&g_B[d * 128 + lane * 4];
    float4 w = *(const float4*)&w2[lane * 4];
    float sum = fmaxf(a.x + b.x, 0.f) * w.x + fmaxf(a.y + b.y, 0.f) * w.y +
                fmaxf(a.z + b.z, 0.f) * w.z + fmaxf(a.w + b.w, 0.f) * w.w;
#pragma unroll
    for (int off = 16; off; off >>= 1) sum += __shfl_down_sync(0xffffffffu, sum, off);
    if (lane == 0) out[e] = 1.f / (1.f + expf(-(sum + b2[0])));
}

// ---------------- host ----------------
extern "C" void kernel_launch(void* const* d_in, const int* in_sizes, int n_in,
                              void* d_out, int out_size) {
    int b = (in_sizes[0] == 2 * EE) ? 2 : 0;
    const int* eidx = (const int*)(b ? d_in[0] : d_in[24]);
    const int* etype = (const int*)(b ? d_in[1] : d_in[25]);
    const int* src = eidx;
    const int* dst = eidx + EE;
    auto F = [&](int i) { return (const float*)d_in[i]; };

    zero_k<<<(2 * NN + 255) / 256, 256>>>();
    count_k<<<(EE + 255) / 256, 256>>>(etype, dst);
    scan_k<<<1, 1024>>>();
    scatter_k<<<(EE + 255) / 256, 256>>>(src, dst, etype);

    int ptot = R0 + 4096 + 8192 + 4096;
    precomp_k<<<(ptot + 255) / 256, 256>>>(F(b + 0), F(b + 1),
                                           F(b + 4), F(b + 5),
                                           F(b + 8), F(b + 9),
                                           F(b + 12), F(b + 13));
    l0_agg_k<<<NN / 4, 128>>>(F(b + 2), F(b + 3));

    // L1: x->y, L2: y->x, L3: x->y
    aggx_k<<<NN / 4, 128>>>(32, g_x);
    { dim3 blk(64, 4); rgcn_gemm2_k<<<NN / 4, blk>>>(F(b + 6), F(b + 7), g_W1, 32, 64, g_x, g_y); }
    aggx_k<<<NN / 4, 128>>>(64, g_y);
    { dim3 blk(64, 4); rgcn_gemm2_k<<<NN / 4, blk>>>(F(b + 10), F(b + 11), g_W2, 64, 64, g_y, g_x); }
    aggx_k<<<NN / 4, 128>>>(64, g_x);
    { dim3 blk(32, 4); rgcn_gemm2_k<<<NN / 4, blk>>>(F(b + 14), F(b + 15), g_W3, 64, 32, g_x, g_y); }

    gat_h_k<<<NN, 256>>>(F(b + 16), F(b + 17), F(b + 18));
    gat_node_k<<<NN, 128>>>();

    dim3 abgrid((NN + 63) / 64, 2);
    ab_gemm_k<<<abgrid, 256>>>(F(b + 20), F(b + 21), F(b + 19));
    final_k<<<(EE + 3) / 4, 128>>>(src, dst, F(b + 22), F(b + 23), (float*)d_out);
}

// round 6
// speedup vs baseline: 2.7452x; 2.6634x over previous
#include <cuda_runtime.h>
#include <cuda_bf16.h>
#include <math.h>

#define NN 6000
#define EE 100000

// ---------------- scratch ----------------
__device__ float g_x[NN * 64];          // ping
__device__ float g_y[NN * 64];          // pong
__device__ float g_base[NN * 32];       // layer0 root term
__device__ float g_hr[2 * NN * 32];     // layer0 relation rows
__device__ float g_s[2 * NN * 64];      // per-relation aggregated inputs (mean-scaled)
__device__ float g_Wcat[64 * 128];      // [I, 2*O]
__device__ int   g_cnt[2 * NN];
__device__ float g_rinv[2 * NN];
__device__ int   g_deg[NN];
__device__ int   g_offs[NN + 1];
__device__ int   g_cur[NN];
__device__ int   g_csr[EE];             // packed src | (rel<<16)
__device__ float g_h[NN * 512];
__device__ float g_asv[NN], g_adv[NN];
__device__ float g_o512[NN * 512];
__device__ float g_A[NN * 128], g_B[NN * 128];

// ---------------- CSR build ----------------
__global__ void zero_k() {
    int i = blockIdx.x * blockDim.x + threadIdx.x;
    if (i < 2 * NN) g_cnt[i] = 0;
    if (i < NN) { g_deg[i] = 0; g_cur[i] = 0; }
}
__global__ void count_k(const int* __restrict__ et, const int* __restrict__ dst) {
    int e = blockIdx.x * blockDim.x + threadIdx.x;
    if (e < EE) {
        int d = dst[e];
        atomicAdd(&g_deg[d], 1);
        atomicAdd(&g_cnt[et[e] * NN + d], 1);
    }
}
__global__ void scan_k() {
    __shared__ int ws[32];
    int t = threadIdx.x;                 // 1024 threads
    int base = t * 6;
    int loc[6]; int s = 0;
#pragma unroll
    for (int j = 0; j < 6; j++) {
        int idx = base + j; loc[j] = s;
        s += (idx < NN) ? g_deg[idx] : 0;
    }
    int lane = t & 31, w = t >> 5;
    int v = s;
#pragma unroll
    for (int off = 1; off < 32; off <<= 1) {
        int nv = __shfl_up_sync(0xffffffffu, v, off);
        if (lane >= off) v += nv;
    }
    if (lane == 31) ws[w] = v;
    __syncthreads();
    if (w == 0) {
        int x = ws[lane];
#pragma unroll
        for (int off = 1; off < 32; off <<= 1) {
            int nv = __shfl_up_sync(0xffffffffu, x, off);
            if (lane >= off) x += nv;
        }
        ws[lane] = x;
    }
    __syncthreads();
    int excl = v - s + (w ? ws[w - 1] : 0);
#pragma unroll
    for (int j = 0; j < 6; j++) {
        int idx = base + j;
        if (idx < NN) g_offs[idx] = excl + loc[j];
    }
    if (t == 1023) g_offs[NN] = excl + s;
}
__global__ void scatter_k(const int* __restrict__ src, const int* __restrict__ dst,
                          const int* __restrict__ et) {
    int e = blockIdx.x * blockDim.x + threadIdx.x;
    if (e >= EE) return;
    int d = dst[e];
    int pos = g_offs[d] + atomicAdd(&g_cur[d], 1);
    g_csr[pos] = src[e] | (et[e] << 16);
}
__global__ void rinv_k() {
    int i = blockIdx.x * blockDim.x + threadIdx.x;
    if (i < 2 * NN) g_rinv[i] = 1.0f / fmaxf((float)g_cnt[i], 1.0f);
}

// ---------------- layer 0 (identity input shortcut) ----------------
__global__ void l0_hr_k(const float* __restrict__ basis0, const float* __restrict__ comp0) {
    int i = blockIdx.x * blockDim.x + threadIdx.x;
    if (i >= 2 * NN * 32) return;
    int r = i / (NN * 32), idx = i % (NN * 32);
    float acc = 0.f;
#pragma unroll
    for (int b = 0; b < 4; b++) acc += comp0[r * 4 + b] * basis0[b * NN * 32 + idx];
    g_hr[r * NN * 32 + idx] = acc;
}
__global__ void l0_base_k(const float* __restrict__ root0, const float* __restrict__ rbias0) {
    int i = blockIdx.x * blockDim.x + threadIdx.x;
    if (i < NN * 32) g_base[i] = root0[i] + rbias0[i & 31];
}
// warp per node, lane = channel (32). Gather-aggregate + finalize + tanh.
__global__ void l0_agg_k() {
    int n = blockIdx.x * 4 + (threadIdx.x >> 5);
    int lane = threadIdx.x & 31;
    if (n >= NN) return;
    int o = g_offs[n], e2 = g_offs[n + 1];
    float a0 = 0.f, a1 = 0.f;
    for (int p = o; p < e2; p++) {
        int pk = g_csr[p];
        float v = g_hr[(pk >> 16) * NN * 32 + (pk & 0xffff) * 32 + lane];
        if (pk & 0x10000) a1 += v; else a0 += v;
    }
    float out = g_base[n * 32 + lane] + a0 * g_rinv[n] + a1 * g_rinv[NN + n];
    g_x[n * 32 + lane] = tanhf(out);
}

// ---------------- RGCN layers 1..3 ----------------
__global__ void wcat_k(const float* __restrict__ basis, const float* __restrict__ comp,
                       int I, int O) {
    int i = blockIdx.x * blockDim.x + threadIdx.x;
    if (i >= 2 * I * O) return;
    int r = i / (I * O), io = i % (I * O);
    float acc = 0.f;
#pragma unroll
    for (int b = 0; b < 4; b++) acc += comp[r * 4 + b] * basis[b * I * O + io];
    int irow = io / O, c = io % O;
    g_Wcat[irow * 2 * O + r * O + c] = acc;
}
// warp per node: aggregate input features per relation (mean-scaled).
__global__ void aggx_k(int I, int inflag) {
    const float* xin = inflag ? g_y : g_x;
    int n = blockIdx.x * 4 + (threadIdx.x >> 5);
    int lane = threadIdx.x & 31;
    if (n >= NN) return;
    int o = g_offs[n], e2 = g_offs[n + 1];
    float a00 = 0.f, a01 = 0.f, a10 = 0.f, a11 = 0.f;
    for (int p = o; p < e2; p++) {
        int pk = g_csr[p];
        int s = pk & 0xffff;
        float v0 = xin[s * I + lane];
        float v1 = (I == 64) ? xin[s * I + lane + 32] : 0.f;
        if (pk & 0x10000) { a10 += v0; a11 += v1; }
        else              { a00 += v0; a01 += v1; }
    }
    float r0 = g_rinv[n], r1 = g_rinv[NN + n];
    g_s[n * I + lane] = a00 * r0;
    g_s[NN * I + n * I + lane] = a10 * r1;
    if (I == 64) {
        g_s[n * I + lane + 32] = a01 * r0;
        g_s[NN * I + n * I + lane + 32] = a11 * r1;
    }
}
// block: (O, 4) threads, 4 nodes. out = tanh(x@root + agg0@W0 + agg1@W1 + bias)
__global__ void rgcn_gemm2_k(const float* __restrict__ root, const float* __restrict__ rbias,
                             int I, int O, int inflag) {
    __shared__ float xs[4][64], a0s[4][64], a1s[4][64];
    const float* xin = inflag ? g_y : g_x;
    float* xout = inflag ? g_x : g_y;
    int ty = threadIdx.y, tx = threadIdx.x;
    int n = blockIdx.x * 4 + ty;
    for (int i = tx; i < I; i += O) {
        xs[ty][i]  = xin[n * I + i];
        a0s[ty][i] = g_s[n * I + i];
        a1s[ty][i] = g_s[NN * I + n * I + i];
    }
    __syncthreads();
    float acc = rbias[tx];
#pragma unroll 8
    for (int i = 0; i < I; i++) {
        acc += xs[ty][i] * root[i * O + tx];
        acc += a0s[ty][i] * g_Wcat[i * 2 * O + tx];
        acc += a1s[ty][i] * g_Wcat[i * 2 * O + O + tx];
    }
    xout[n * O + tx] = tanhf(acc);
}

// ---------------- GAT ----------------
__global__ void gat_h_k(const float* __restrict__ gw, const float* __restrict__ asrc,
                        const float* __restrict__ adst) {
    __shared__ float xs[32];
    __shared__ float reda[8], redd[8];
    int n = blockIdx.x, tid = threadIdx.x;
    if (tid < 32) xs[tid] = g_y[n * 32 + tid];   // layer3 output lives in g_y
    __syncthreads();
    float a0 = 0.f, a1 = 0.f;
    int c0 = tid, c1 = tid + 256;
#pragma unroll 8
    for (int i = 0; i < 32; i++) {
        float xv = xs[i];
        a0 += xv * gw[i * 512 + c0];
        a1 += xv * gw[i * 512 + c1];
    }
    g_h[n * 512 + c0] = a0;
    g_h[n * 512 + c1] = a1;
    float pa = a0 * asrc[c0] + a1 * asrc[c1];
    float pd = a0 * adst[c0] + a1 * adst[c1];
#pragma unroll
    for (int off = 16; off; off >>= 1) {
        pa += __shfl_down_sync(0xffffffffu, pa, off);
        pd += __shfl_down_sync(0xffffffffu, pd, off);
    }
    if ((tid & 31) == 0) { reda[tid >> 5] = pa; redd[tid >> 5] = pd; }
    __syncthreads();
    if (tid == 0) {
        float sa = 0.f, sd = 0.f;
#pragma unroll
        for (int w = 0; w < 8; w++) { sa += reda[w]; sd += redd[w]; }
        g_asv[n] = sa;
        g_adv[n] = sd;
    }
}
// block(128) per node: softmax over incoming edges + self-loop, then gather-weighted sum.
__global__ void gat_node_k() {
    __shared__ float sal[2048];
    __shared__ float red[128];
    int n = blockIdx.x, tid = threadIdx.x;
    int o = g_offs[n];
    int deg = g_offs[n + 1] - o;
    if (deg > 2048) deg = 2048;
    float advn = g_adv[n];
    float lm = -1e30f;
    for (int p = tid; p < deg; p += 128) {
        int s = g_csr[o + p] & 0xffff;
        float a = g_asv[s] + advn;
        a = a > 0.f ? a : 0.2f * a;
        sal[p] = a;
        lm = fmaxf(lm, a);
    }
    float als = g_asv[n] + advn;
    als = als > 0.f ? als : 0.2f * als;
    lm = fmaxf(lm, als);
    red[tid] = lm; __syncthreads();
    for (int st = 64; st; st >>= 1) {
        if (tid < st) red[tid] = fmaxf(red[tid], red[tid + st]);
        __syncthreads();
    }
    float m = red[0];
    __syncthreads();
    float ls = 0.f;
    for (int p = tid; p < deg; p += 128) {
        float ex = expf(sal[p] - m);
        sal[p] = ex;
        ls += ex;
    }
    float exs = expf(als - m);
    if (tid == 0) ls += exs;
    red[tid] = ls; __syncthreads();
    for (int st = 64; st; st >>= 1) {
        if (tid < st) red[tid] += red[tid + st];
        __syncthreads();
    }
    float invden = 1.f / fmaxf(red[0], 1e-16f);
    // weighted sum: thread tid owns cols 4*tid..4*tid+3
    float cs = exs * invden;
    float4 hv = ((const float4*)&g_h[n * 512])[tid];
    float4 acc;
    acc.x = cs * hv.x; acc.y = cs * hv.y; acc.z = cs * hv.z; acc.w = cs * hv.w;
    for (int p = 0; p < deg; p++) {
        int s = g_csr[o + p] & 0xffff;
        float c = sal[p] * invden;
        float4 h4 = ((const float4*)&g_h[s * 512])[tid];
        acc.x += c * h4.x; acc.y += c * h4.y; acc.z += c * h4.z; acc.w += c * h4.w;
    }
    ((float4*)&g_o512[n * 512])[tid] = acc;
}

// ---------------- AB GEMM (THE ONE CHANGE vs R2): 64M x 128N tile, BK=16, 4x8/thread ----------------
__global__ void ab_gemm_k(const float* __restrict__ w1, const float* __restrict__ b1,
                          const float* __restrict__ gbias) {
    __shared__ float As[16][68];
    __shared__ float Bs[16][128];
    int tid = threadIdx.x;
    int bm = blockIdx.x * 64;
    int by = blockIdx.y;           // 0 -> g_A half (w1 rows 0..511), 1 -> g_B half
    int ty = tid >> 4, tx = tid & 15;
    float acc[4][8] = {};
    for (int k0 = 0; k0 < 512; k0 += 16) {
        {
            int mm = tid & 63, kg = tid >> 6;
            int gm = bm + mm;
            float4 v = make_float4(0.f, 0.f, 0.f, 0.f);
            if (gm < NN) v = *(const float4*)&g_o512[gm * 512 + k0 + kg * 4];
            const float4 gb = *(const float4*)&gbias[k0 + kg * 4];
            As[kg * 4 + 0][mm] = fmaxf(v.x + gb.x, 0.f);
            As[kg * 4 + 1][mm] = fmaxf(v.y + gb.y, 0.f);
            As[kg * 4 + 2][mm] = fmaxf(v.z + gb.z, 0.f);
            As[kg * 4 + 3][mm] = fmaxf(v.w + gb.w, 0.f);
        }
        {
            int id = tid * 4;
#pragma unroll
            for (int rep = 0; rep < 2; rep++, id += 1024) {
                int kk = id >> 7, col = id & 127;
                float4 v = *(const float4*)&w1[(k0 + kk + by * 512) * 128 + col];
                *(float4*)&Bs[kk][col] = v;
            }
        }
        __syncthreads();
#pragma unroll
        for (int kk = 0; kk < 16; kk++) {
            float a[4], bb[8];
#pragma unroll
            for (int i = 0; i < 4; i++) a[i] = As[kk][ty * 4 + i];
#pragma unroll
            for (int j = 0; j < 8; j++) bb[j] = Bs[kk][tx * 8 + j];
#pragma unroll
            for (int i = 0; i < 4; i++)
#pragma unroll
                for (int j = 0; j < 8; j++) acc[i][j] += a[i] * bb[j];
        }
        __syncthreads();
    }
    float* dstbuf = by == 0 ? g_A : g_B;
#pragma unroll
    for (int i = 0; i < 4; i++) {
        int gm = bm + ty * 4 + i;
        if (gm >= NN) continue;
#pragma unroll
        for (int j = 0; j < 8; j++) {
            int c = tx * 8 + j;
            float v = acc[i][j];
            if (by == 0) v += b1[c];
            dstbuf[gm * 128 + c] = v;
        }
    }
}

__global__ void final_k(const int* __restrict__ src, const int* __restrict__ dst,
                        const float* __restrict__ w2, const float* __restrict__ b2,
                        float* __restrict__ out) {
    int e = blockIdx.x * 4 + (threadIdx.x >> 5);
    int lane = threadIdx.x & 31;
    if (e >= EE) return;
    int s = src[e], d = dst[e];
    float4 a = *(const float4*)&g_A[s * 128 + lane * 4];
    float4 b = *(const float4*)&g_B[d * 128 + lane * 4];
    float4 w = *(const float4*)&w2[lane * 4];
    float sum = fmaxf(a.x + b.x, 0.f) * w.x + fmaxf(a.y + b.y, 0.f) * w.y +
                fmaxf(a.z + b.z, 0.f) * w.z + fmaxf(a.w + b.w, 0.f) * w.w;
#pragma unroll
    for (int off = 16; off; off >>= 1) sum += __shfl_down_sync(0xffffffffu, sum, off);
    if (lane == 0) out[e] = 1.f / (1.f + expf(-(sum + b2[0])));
}

// ---------------- host ----------------
extern "C" void kernel_launch(void* const* d_in, const int* in_sizes, int n_in,
                              void* d_out, int out_size) {
    int b = (in_sizes[0] == 2 * EE) ? 2 : 0;
    const int* eidx = (const int*)(b ? d_in[0] : d_in[24]);
    const int* etype = (const int*)(b ? d_in[1] : d_in[25]);
    const int* src = eidx;
    const int* dst = eidx + EE;
    auto F = [&](int i) { return (const float*)d_in[i]; };

    // CSR build + degree counts
    zero_k<<<(2 * NN + 255) / 256, 256>>>();
    count_k<<<(EE + 255) / 256, 256>>>(etype, dst);
    scan_k<<<1, 1024>>>();
    scatter_k<<<(EE + 255) / 256, 256>>>(src, dst, etype);
    rinv_k<<<(2 * NN + 255) / 256, 256>>>();

    // layer 0
    l0_hr_k<<<(2 * NN * 32 + 255) / 256, 256>>>(F(b + 0), F(b + 1));
    l0_base_k<<<(NN * 32 + 255) / 256, 256>>>(F(b + 2), F(b + 3));
    l0_agg_k<<<NN / 4, 128>>>();

    // layers 1..3 (ping-pong: L1 x->y, L2 y->x, L3 x->y)
    const int Is[3] = {32, 64, 64};
    const int Os[3] = {64, 64, 32};
    const int inflags[3] = {0, 1, 0};
    for (int l = 1; l < 4; l++) {
        int I = Is[l - 1], O = Os[l - 1];
        wcat_k<<<(2 * I * O + 255) / 256, 256>>>(F(b + 4 * l), F(b + 4 * l + 1), I, O);
        aggx_k<<<NN / 4, 128>>>(I, inflags[l - 1]);
        dim3 blk(O, 4);
        rgcn_gemm2_k<<<NN / 4, blk>>>(F(b + 4 * l + 2), F(b + 4 * l + 3), I, O, inflags[l - 1]);
    }

    // GAT
    gat_h_k<<<NN, 256>>>(F(b + 16), F(b + 17), F(b + 18));
    gat_node_k<<<NN, 128>>>();

    // edge MLP
    dim3 abgrid((NN + 63) / 64, 2);
    ab_gemm_k<<<abgrid, 256>>>(F(b + 20), F(b + 21), F(b + 19));
    final_k<<<(EE + 3) / 4, 128>>>(src, dst, F(b + 22), F(b + 23), (float*)d_out);
}

// round 7
// speedup vs baseline: 3.0536x; 1.1123x over previous
#include <cuda_runtime.h>
#include <cuda_bf16.h>
#include <math.h>

#define NN 6000
#define EE 100000

// ---------------- scratch (device-only; NEVER passed from host) ----------------
__device__ float g_x[NN * 64];          // ping
__device__ float g_y[NN * 64];          // pong
__device__ float g_hr[2 * NN * 32];     // layer0 relation rows
__device__ float g_W1[32 * 128];        // [I, 2*O]
__device__ float g_W2[64 * 128];
__device__ float g_W3[64 * 64];
__device__ int   g_cnt[2 * NN];
__device__ float g_rinv[2 * NN];
__device__ int   g_offs[NN + 1];
__device__ int   g_cur[NN];
__device__ int   g_csr[EE];             // src | (rel<<16)
__device__ float g_h[NN * 512];
__device__ float g_asv[NN], g_adv[NN];
__device__ float g_o512[NN * 512];
__device__ float g_A[NN * 128], g_B[NN * 128];

// ---------------- CSR build ----------------
__global__ void zero_k() {
    int i = blockIdx.x * blockDim.x + threadIdx.x;
    if (i < 2 * NN) g_cnt[i] = 0;
    if (i < NN) g_cur[i] = 0;
}
__global__ void count_k(const int* __restrict__ et, const int* __restrict__ dst) {
    int e = blockIdx.x * blockDim.x + threadIdx.x;
    if (e < EE) atomicAdd(&g_cnt[et[e] * NN + dst[e]], 1);
}
// scan of deg (=cnt0+cnt1) + rinv, single block 1024 threads
__global__ void scan_k() {
    __shared__ int ws[32];
    int t = threadIdx.x;
    for (int i = t; i < 2 * NN; i += 1024)
        g_rinv[i] = 1.0f / fmaxf((float)g_cnt[i], 1.0f);
    int base = t * 6;
    int loc[6]; int s = 0;
#pragma unroll
    for (int j = 0; j < 6; j++) {
        int idx = base + j; loc[j] = s;
        s += (idx < NN) ? (g_cnt[idx] + g_cnt[NN + idx]) : 0;
    }
    int lane = t & 31, w = t >> 5;
    int v = s;
#pragma unroll
    for (int off = 1; off < 32; off <<= 1) {
        int nv = __shfl_up_sync(0xffffffffu, v, off);
        if (lane >= off) v += nv;
    }
    if (lane == 31) ws[w] = v;
    __syncthreads();
    if (w == 0) {
        int x = ws[lane];
#pragma unroll
        for (int off = 1; off < 32; off <<= 1) {
            int nv = __shfl_up_sync(0xffffffffu, x, off);
            if (lane >= off) x += nv;
        }
        ws[lane] = x;
    }
    __syncthreads();
    int excl = v - s + (w ? ws[w - 1] : 0);
#pragma unroll
    for (int j = 0; j < 6; j++) {
        int idx = base + j;
        if (idx < NN) g_offs[idx] = excl + loc[j];
    }
    if (t == 1023) g_offs[NN] = excl + s;
}
__global__ void scatter_k(const int* __restrict__ src, const int* __restrict__ dst,
                          const int* __restrict__ et) {
    int e = blockIdx.x * blockDim.x + threadIdx.x;
    if (e >= EE) return;
    int d = dst[e];
    int pos = g_offs[d] + atomicAdd(&g_cur[d], 1);
    g_csr[pos] = src[e] | (et[e] << 16);
}

// ---------------- fused precompute: l0_hr + Wcat 1..3 ----------------
__device__ __forceinline__ void wcat_one(float* W, const float* basis, const float* comp,
                                         int I, int O, int i) {
    int r = i / (I * O), io = i % (I * O);
    float acc = 0.f;
#pragma unroll
    for (int b = 0; b < 4; b++) acc += comp[r * 4 + b] * basis[b * I * O + io];
    W[(io / O) * 2 * O + r * O + (io % O)] = acc;
}
#define R0 (2 * NN * 32)
__global__ void precomp_k(const float* __restrict__ basis0, const float* __restrict__ comp0,
                          const float* __restrict__ b1s, const float* __restrict__ c1,
                          const float* __restrict__ b2s, const float* __restrict__ c2,
                          const float* __restrict__ b3s, const float* __restrict__ c3) {
    int i = blockIdx.x * blockDim.x + threadIdx.x;
    if (i < R0) {
        int r = i / (NN * 32), idx = i % (NN * 32);
        float acc = 0.f;
#pragma unroll
        for (int b = 0; b < 4; b++) acc += comp0[r * 4 + b] * basis0[b * NN * 32 + idx];
        g_hr[r * NN * 32 + idx] = acc;
    } else if (i < R0 + 4096) {
        wcat_one(g_W1, b1s, c1, 32, 64, i - R0);
    } else if (i < R0 + 4096 + 8192) {
        wcat_one(g_W2, b2s, c2, 64, 64, i - R0 - 4096);
    } else if (i < R0 + 4096 + 8192 + 4096) {
        wcat_one(g_W3, b3s, c3, 64, 32, i - R0 - 4096 - 8192);
    }
}

// ---------------- layer 0: gather + root + bias + tanh ----------------
__global__ void l0_agg_k(const float* __restrict__ root0, const float* __restrict__ rbias0) {
    int n = blockIdx.x * 4 + (threadIdx.x >> 5);
    int lane = threadIdx.x & 31;
    if (n >= NN) return;
    int o = g_offs[n], e2 = g_offs[n + 1];
    float a0 = 0.f, a1 = 0.f;
    for (int p = o; p < e2; p++) {
        int pk = g_csr[p];
        float v = g_hr[(pk >> 16) * NN * 32 + (pk & 0xffff) * 32 + lane];
        if (pk & 0x10000) a1 += v; else a0 += v;
    }
    float out = root0[n * 32 + lane] + rbias0[lane] + a0 * g_rinv[n] + a1 * g_rinv[NN + n];
    g_x[n * 32 + lane] = tanhf(out);
}

// ---------------- fused RGCN layer: aggregate + GEMM + tanh ----------------
// blockDim (64,4), 4 nodes/block. layer selects weight buffer device-side.
__global__ void layer_k(const float* __restrict__ root, const float* __restrict__ rbias,
                        int layer, int I, int O, int inflag) {
    __shared__ float xs[4][64], a0s[4][64], a1s[4][64];
    const float* xin = inflag ? g_y : g_x;
    float* xout = inflag ? g_x : g_y;
    const float* Wcat = (layer == 1) ? g_W1 : (layer == 2) ? g_W2 : g_W3;
    int ty = threadIdx.y, tx = threadIdx.x;
    int n = blockIdx.x * 4 + ty;
    if (tx < I) {
        int o = g_offs[n], e2 = g_offs[n + 1];
        float a0 = 0.f, a1 = 0.f;
        for (int p = o; p < e2; p++) {
            int pk = g_csr[p];
            float v = xin[(pk & 0xffff) * I + tx];
            if (pk & 0x10000) a1 += v; else a0 += v;
        }
        xs[ty][tx] = xin[n * I + tx];
        a0s[ty][tx] = a0 * g_rinv[n];
        a1s[ty][tx] = a1 * g_rinv[NN + n];
    }
    __syncthreads();
    if (tx < O) {
        float acc = rbias[tx];
#pragma unroll 8
        for (int i = 0; i < I; i++) {
            acc += xs[ty][i] * root[i * O + tx];
            acc += a0s[ty][i] * Wcat[i * 2 * O + tx];
            acc += a1s[ty][i] * Wcat[i * 2 * O + O + tx];
        }
        xout[n * O + tx] = tanhf(acc);
    }
}

// ---------------- GAT h GEMM: g_h[6000,512] = g_y[6000,32] @ gw[32,512] ----------------
// tile 64M x 128N, K=32 single shot, 256 threads, 4x8/thread (ab_gemm pattern)
__global__ void gath_gemm_k(const float* __restrict__ gw) {
    __shared__ float As[32][68];
    __shared__ float Bs[32][128];
    int tid = threadIdx.x;
    int bm = blockIdx.x * 64, bn = blockIdx.y * 128;
    int ty = tid >> 4, tx = tid & 15;
    // load A: 64 rows x 32 cols = 2048 floats; 8 per thread (2 x float4)
    {
        int mm = tid & 63, kg = tid >> 6;   // kg in 0..3, each covers 8 cols
#pragma unroll
        for (int r = 0; r < 2; r++) {
            int k = kg * 8 + r * 4;
            int gm = bm + mm;
            float4 v = make_float4(0.f, 0.f, 0.f, 0.f);
            if (gm < NN) v = *(const float4*)&g_y[gm * 32 + k];
            As[k + 0][mm] = v.x; As[k + 1][mm] = v.y;
            As[k + 2][mm] = v.z; As[k + 3][mm] = v.w;
        }
    }
    // load B: 32 rows x 128 cols = 4096 floats; 16 per thread (4 x float4)
    {
        int id = tid * 4;
#pragma unroll
        for (int rep = 0; rep < 4; rep++, id += 1024) {
            int kk = id >> 7, col = id & 127;
            *(float4*)&Bs[kk][col] = *(const float4*)&gw[kk * 512 + bn + col];
        }
    }
    __syncthreads();
    float acc[4][8] = {};
#pragma unroll
    for (int kk = 0; kk < 32; kk++) {
        float a[4], bb[8];
#pragma unroll
        for (int i = 0; i < 4; i++) a[i] = As[kk][ty * 4 + i];
#pragma unroll
        for (int j = 0; j < 8; j++) bb[j] = Bs[kk][tx * 8 + j];
#pragma unroll
        for (int i = 0; i < 4; i++)
#pragma unroll
            for (int j = 0; j < 8; j++) acc[i][j] += a[i] * bb[j];
    }
#pragma unroll
    for (int i = 0; i < 4; i++) {
        int gm = bm + ty * 4 + i;
        if (gm >= NN) continue;
#pragma unroll
        for (int j = 0; j < 8; j += 4) {
            float4 st = make_float4(acc[i][j], acc[i][j + 1], acc[i][j + 2], acc[i][j + 3]);
            *(float4*)&g_h[gm * 512 + bn + tx * 8 + j] = st;
        }
    }
}

// per-node attention logits: asv = h·a_src, adv = h·a_dst. block(128) per node.
__global__ void attn_k(const float* __restrict__ asrc, const float* __restrict__ adst) {
    __shared__ float reda[4], redd[4];
    int n = blockIdx.x, tid = threadIdx.x;
    float4 hv = ((const float4*)&g_h[n * 512])[tid];
    float4 sa = ((const float4*)asrc)[tid];
    float4 da = ((const float4*)adst)[tid];
    float pa = hv.x * sa.x + hv.y * sa.y + hv.z * sa.z + hv.w * sa.w;
    float pd = hv.x * da.x + hv.y * da.y + hv.z * da.z + hv.w * da.w;
#pragma unroll
    for (int off = 16; off; off >>= 1) {
        pa += __shfl_down_sync(0xffffffffu, pa, off);
        pd += __shfl_down_sync(0xffffffffu, pd, off);
    }
    if ((tid & 31) == 0) { reda[tid >> 5] = pa; redd[tid >> 5] = pd; }
    __syncthreads();
    if (tid == 0) {
        g_asv[n] = reda[0] + reda[1] + reda[2] + reda[3];
        g_adv[n] = redd[0] + redd[1] + redd[2] + redd[3];
    }
}

// ---------------- GAT per-node softmax + weighted sum ----------------
__global__ void gat_node_k() {
    __shared__ float sal[512];
    __shared__ int ssrc[512];
    __shared__ float red[128];
    int n = blockIdx.x, tid = threadIdx.x;
    int o = g_offs[n];
    int deg = g_offs[n + 1] - o;
    if (deg > 512) deg = 512;
    float advn = g_adv[n];
    float lm = -1e30f;
    for (int p = tid; p < deg; p += 128) {
        int s = g_csr[o + p] & 0xffff;
        ssrc[p] = s;
        float a = g_asv[s] + advn;
        a = a > 0.f ? a : 0.2f * a;
        sal[p] = a;
        lm = fmaxf(lm, a);
    }
    float als = g_asv[n] + advn;
    als = als > 0.f ? als : 0.2f * als;
    lm = fmaxf(lm, als);
    red[tid] = lm; __syncthreads();
    for (int st = 64; st; st >>= 1) {
        if (tid < st) red[tid] = fmaxf(red[tid], red[tid + st]);
        __syncthreads();
    }
    float m = red[0];
    __syncthreads();
    float ls = 0.f;
    for (int p = tid; p < deg; p += 128) {
        float ex = expf(sal[p] - m);
        sal[p] = ex;
        ls += ex;
    }
    float exs = expf(als - m);
    if (tid == 0) ls += exs;
    red[tid] = ls; __syncthreads();
    for (int st = 64; st; st >>= 1) {
        if (tid < st) red[tid] += red[tid + st];
        __syncthreads();
    }
    float invden = 1.f / fmaxf(red[0], 1e-16f);
    float cs = exs * invden;
    float4 hv = ((const float4*)&g_h[n * 512])[tid];
    float4 acc;
    acc.x = cs * hv.x; acc.y = cs * hv.y; acc.z = cs * hv.z; acc.w = cs * hv.w;
#pragma unroll 4
    for (int p = 0; p < deg; p++) {
        int s = ssrc[p];
        float c = sal[p] * invden;
        float4 h4 = ((const float4*)&g_h[s * 512])[tid];
        acc.x += c * h4.x; acc.y += c * h4.y; acc.z += c * h4.z; acc.w += c * h4.w;
    }
    ((float4*)&g_o512[n * 512])[tid] = acc;
}

// ---------------- AB GEMM: 64M x 128N tile, BK=16, 4x8/thread (verified R5) ----------------
__global__ void ab_gemm_k(const float* __restrict__ w1, const float* __restrict__ b1,
                          const float* __restrict__ gbias) {
    __shared__ float As[16][68];
    __shared__ float Bs[16][128];
    int tid = threadIdx.x;
    int bm = blockIdx.x * 64;
    int by = blockIdx.y;           // 0 -> g_A half (w1 rows 0..511), 1 -> g_B half
    int ty = tid >> 4, tx = tid & 15;
    float acc[4][8] = {};
    for (int k0 = 0; k0 < 512; k0 += 16) {
        {
            int mm = tid & 63, kg = tid >> 6;
            int gm = bm + mm;
            float4 v = make_float4(0.f, 0.f, 0.f, 0.f);
            if (gm < NN) v = *(const float4*)&g_o512[gm * 512 + k0 + kg * 4];
            const float4 gb = *(const float4*)&gbias[k0 + kg * 4];
            As[kg * 4 + 0][mm] = fmaxf(v.x + gb.x, 0.f);
            As[kg * 4 + 1][mm] = fmaxf(v.y + gb.y, 0.f);
            As[kg * 4 + 2][mm] = fmaxf(v.z + gb.z, 0.f);
            As[kg * 4 + 3][mm] = fmaxf(v.w + gb.w, 0.f);
        }
        {
            int id = tid * 4;
#pragma unroll
            for (int rep = 0; rep < 2; rep++, id += 1024) {
                int kk = id >> 7, col = id & 127;
                float4 v = *(const float4*)&w1[(k0 + kk + by * 512) * 128 + col];
                *(float4*)&Bs[kk][col] = v;
            }
        }
        __syncthreads();
#pragma unroll
        for (int kk = 0; kk < 16; kk++) {
            float a[4], bb[8];
#pragma unroll
            for (int i = 0; i < 4; i++) a[i] = As[kk][ty * 4 + i];
#pragma unroll
            for (int j = 0; j < 8; j++) bb[j] = Bs[kk][tx * 8 + j];
#pragma unroll
            for (int i = 0; i < 4; i++)
#pragma unroll
                for (int j = 0; j < 8; j++) acc[i][j] += a[i] * bb[j];
        }
        __syncthreads();
    }
#pragma unroll
    for (int i = 0; i < 4; i++) {
        int gm = bm + ty * 4 + i;
        if (gm >= NN) continue;
#pragma unroll
        for (int j = 0; j < 8; j++) {
            int c = tx * 8 + j;
            float v = acc[i][j];
            if (by == 0) v += b1[c];
            if (by == 0) g_A[gm * 128 + c] = v;
            else         g_B[gm * 128 + c] = v;
        }
    }
}

__global__ void final_k(const int* __restrict__ src, const int* __restrict__ dst,
                        const float* __restrict__ w2, const float* __restrict__ b2,
                        float* __restrict__ out) {
    int e = blockIdx.x * 4 + (threadIdx.x >> 5);
    int lane = threadIdx.x & 31;
    if (e >= EE) return;
    int s = src[e], d = dst[e];
    float4 a = *(const float4*)&g_A[s * 128 + lane * 4];
    float4 b = *(const float4*)&g_B[d * 128 + lane * 4];
    float4 w = *(const float4*)&w2[lane * 4];
    float sum = fmaxf(a.x + b.x, 0.f) * w.x + fmaxf(a.y + b.y, 0.f) * w.y +
                fmaxf(a.z + b.z, 0.f) * w.z + fmaxf(a.w + b.w, 0.f) * w.w;
#pragma unroll
    for (int off = 16; off; off >>= 1) sum += __shfl_down_sync(0xffffffffu, sum, off);
    if (lane == 0) out[e] = 1.f / (1.f + expf(-(sum + b2[0])));
}

// ---------------- host ----------------
extern "C" void kernel_launch(void* const* d_in, const int* in_sizes, int n_in,
                              void* d_out, int out_size) {
    int b = (in_sizes[0] == 2 * EE) ? 2 : 0;
    const int* eidx = (const int*)(b ? d_in[0] : d_in[24]);
    const int* etype = (const int*)(b ? d_in[1] : d_in[25]);
    const int* src = eidx;
    const int* dst = eidx + EE;
    auto F = [&](int i) { return (const float*)d_in[i]; };

    // CSR build
    zero_k<<<(2 * NN + 255) / 256, 256>>>();
    count_k<<<(EE + 255) / 256, 256>>>(etype, dst);
    scan_k<<<1, 1024>>>();
    scatter_k<<<(EE + 255) / 256, 256>>>(src, dst, etype);

    // fused precompute
    int ptot = R0 + 4096 + 8192 + 4096;
    precomp_k<<<(ptot + 255) / 256, 256>>>(F(b + 0), F(b + 1), F(b + 4), F(b + 5),
                                           F(b + 8), F(b + 9), F(b + 12), F(b + 13));
    // layer 0
    l0_agg_k<<<NN / 4, 128>>>(F(b + 2), F(b + 3));

    // fused layers 1..3 (L1 x->y, L2 y->x, L3 x->y)
    dim3 blk(64, 4);
    layer_k<<<NN / 4, blk>>>(F(b + 6),  F(b + 7),  1, 32, 64, 0);
    layer_k<<<NN / 4, blk>>>(F(b + 10), F(b + 11), 2, 64, 64, 1);
    layer_k<<<NN / 4, blk>>>(F(b + 14), F(b + 15), 3, 64, 32, 0);

    // GAT
    dim3 hg((NN + 63) / 64, 4);
    gath_gemm_k<<<hg, 256>>>(F(b + 16));
    attn_k<<<NN, 128>>>(F(b + 17), F(b + 18));
    gat_node_k<<<NN, 128>>>();

    // edge MLP
    dim3 abgrid((NN + 63) / 64, 2);
    ab_gemm_k<<<abgrid, 256>>>(F(b + 20), F(b + 21), F(b + 19));
    final_k<<<(EE + 3) / 4, 128>>>(src, dst, F(b + 22), F(b + 23), (float*)d_out);
}

// round 8
// speedup vs baseline: 3.2864x; 1.0763x over previous
#include <cuda_runtime.h>
#include <cuda_bf16.h>
#include <math.h>

#define NN 6000
#define EE 100000

// ---------------- scratch (device-only; NEVER passed from host) ----------------
__device__ float g_x[NN * 64];          // ping
__device__ float g_y[NN * 64];          // pong
__device__ float g_hr[2 * NN * 32];     // layer0 relation rows
__device__ float g_W1[32 * 128];        // [I, 2*O]
__device__ float g_W2[64 * 128];
__device__ float g_W3[64 * 64];
__device__ int   g_cnt[2 * NN];
__device__ float g_rinv[2 * NN];
__device__ int   g_offs[NN + 1];
__device__ int   g_cur[NN];
__device__ int   g_csr[EE];             // src | (rel<<16)
__device__ float g_h[NN * 512];
__device__ float g_asv[NN], g_adv[NN];
__device__ float g_o512[NN * 512];
__device__ float g_A[NN * 128], g_B[NN * 128];

// ---------------- CSR build ----------------
__global__ void zero_k() {
    int i = blockIdx.x * blockDim.x + threadIdx.x;
    if (i < 2 * NN) g_cnt[i] = 0;
    if (i < NN) { g_cur[i] = 0; g_asv[i] = 0.f; g_adv[i] = 0.f; }
}
__global__ void count_k(const int* __restrict__ et, const int* __restrict__ dst) {
    int e = blockIdx.x * blockDim.x + threadIdx.x;
    if (e < EE) atomicAdd(&g_cnt[et[e] * NN + dst[e]], 1);
}
// scan of deg (=cnt0+cnt1) + rinv, single block 1024 threads
__global__ void scan_k() {
    __shared__ int ws[32];
    int t = threadIdx.x;
    for (int i = t; i < 2 * NN; i += 1024)
        g_rinv[i] = 1.0f / fmaxf((float)g_cnt[i], 1.0f);
    int base = t * 6;
    int loc[6]; int s = 0;
#pragma unroll
    for (int j = 0; j < 6; j++) {
        int idx = base + j; loc[j] = s;
        s += (idx < NN) ? (g_cnt[idx] + g_cnt[NN + idx]) : 0;
    }
    int lane = t & 31, w = t >> 5;
    int v = s;
#pragma unroll
    for (int off = 1; off < 32; off <<= 1) {
        int nv = __shfl_up_sync(0xffffffffu, v, off);
        if (lane >= off) v += nv;
    }
    if (lane == 31) ws[w] = v;
    __syncthreads();
    if (w == 0) {
        int x = ws[lane];
#pragma unroll
        for (int off = 1; off < 32; off <<= 1) {
            int nv = __shfl_up_sync(0xffffffffu, x, off);
            if (lane >= off) x += nv;
        }
        ws[lane] = x;
    }
    __syncthreads();
    int excl = v - s + (w ? ws[w - 1] : 0);
#pragma unroll
    for (int j = 0; j < 6; j++) {
        int idx = base + j;
        if (idx < NN) g_offs[idx] = excl + loc[j];
    }
    if (t == 1023) g_offs[NN] = excl + s;
}
__global__ void scatter_k(const int* __restrict__ src, const int* __restrict__ dst,
                          const int* __restrict__ et) {
    int e = blockIdx.x * blockDim.x + threadIdx.x;
    if (e >= EE) return;
    int d = dst[e];
    int pos = g_offs[d] + atomicAdd(&g_cur[d], 1);
    g_csr[pos] = src[e] | (et[e] << 16);
}

// ---------------- fused precompute: l0_hr + Wcat 1..3 ----------------
__device__ __forceinline__ void wcat_one(float* W, const float* basis, const float* comp,
                                         int I, int O, int i) {
    int r = i / (I * O), io = i % (I * O);
    float acc = 0.f;
#pragma unroll
    for (int b = 0; b < 4; b++) acc += comp[r * 4 + b] * basis[b * I * O + io];
    W[(io / O) * 2 * O + r * O + (io % O)] = acc;
}
#define R0 (2 * NN * 32)
__global__ void precomp_k(const float* __restrict__ basis0, const float* __restrict__ comp0,
                          const float* __restrict__ b1s, const float* __restrict__ c1,
                          const float* __restrict__ b2s, const float* __restrict__ c2,
                          const float* __restrict__ b3s, const float* __restrict__ c3) {
    int i = blockIdx.x * blockDim.x + threadIdx.x;
    if (i < R0) {
        int r = i / (NN * 32), idx = i % (NN * 32);
        float acc = 0.f;
#pragma unroll
        for (int b = 0; b < 4; b++) acc += comp0[r * 4 + b] * basis0[b * NN * 32 + idx];
        g_hr[r * NN * 32 + idx] = acc;
    } else if (i < R0 + 4096) {
        wcat_one(g_W1, b1s, c1, 32, 64, i - R0);
    } else if (i < R0 + 4096 + 8192) {
        wcat_one(g_W2, b2s, c2, 64, 64, i - R0 - 4096);
    } else if (i < R0 + 4096 + 8192 + 4096) {
        wcat_one(g_W3, b3s, c3, 64, 32, i - R0 - 4096 - 8192);
    }
}

// ---------------- layer 0: gather + root + bias + tanh ----------------
__global__ void l0_agg_k(const float* __restrict__ root0, const float* __restrict__ rbias0) {
    int n = blockIdx.x * 4 + (threadIdx.x >> 5);
    int lane = threadIdx.x & 31;
    if (n >= NN) return;
    int o = g_offs[n], e2 = g_offs[n + 1];
    float a0 = 0.f, a1 = 0.f;
    for (int p = o; p < e2; p++) {
        int pk = g_csr[p];
        float v = g_hr[(pk >> 16) * NN * 32 + (pk & 0xffff) * 32 + lane];
        if (pk & 0x10000) a1 += v; else a0 += v;
    }
    float out = root0[n * 32 + lane] + rbias0[lane] + a0 * g_rinv[n] + a1 * g_rinv[NN + n];
    g_x[n * 32 + lane] = tanhf(out);
}

// ---------------- fused RGCN layer: aggregate + GEMM + tanh ----------------
__global__ void layer_k(const float* __restrict__ root, const float* __restrict__ rbias,
                        int layer, int I, int O, int inflag) {
    __shared__ float xs[4][64], a0s[4][64], a1s[4][64];
    const float* xin = inflag ? g_y : g_x;
    float* xout = inflag ? g_x : g_y;
    const float* Wcat = (layer == 1) ? g_W1 : (layer == 2) ? g_W2 : g_W3;
    int ty = threadIdx.y, tx = threadIdx.x;
    int n = blockIdx.x * 4 + ty;
    if (tx < I) {
        int o = g_offs[n], e2 = g_offs[n + 1];
        float a0 = 0.f, a1 = 0.f;
#pragma unroll 4
        for (int p = o; p < e2; p++) {
            int pk = g_csr[p];
            float v = xin[(pk & 0xffff) * I + tx];
            if (pk & 0x10000) a1 += v; else a0 += v;
        }
        xs[ty][tx] = xin[n * I + tx];
        a0s[ty][tx] = a0 * g_rinv[n];
        a1s[ty][tx] = a1 * g_rinv[NN + n];
    }
    __syncthreads();
    if (tx < O) {
        float acc = rbias[tx];
#pragma unroll 8
        for (int i = 0; i < I; i++) {
            acc += xs[ty][i] * root[i * O + tx];
            acc += a0s[ty][i] * Wcat[i * 2 * O + tx];
            acc += a1s[ty][i] * Wcat[i * 2 * O + O + tx];
        }
        xout[n * O + tx] = tanhf(acc);
    }
}

// ---------------- GAT h GEMM + fused attention partials ----------------
// tile 64M x 128N, K=32 single shot, 256 threads, 4x8/thread.
// Epilogue: partial asv/adv dots over this block's 128 cols, atomicAdd per row.
__global__ void gath_gemm_k(const float* __restrict__ gw, const float* __restrict__ asrc,
                            const float* __restrict__ adst) {
    __shared__ float As[32][68];
    __shared__ float Bs[32][128];
    int tid = threadIdx.x;
    int bm = blockIdx.x * 64, bn = blockIdx.y * 128;
    int ty = tid >> 4, tx = tid & 15;
    {
        int mm = tid & 63, kg = tid >> 6;
#pragma unroll
        for (int r = 0; r < 2; r++) {
            int k = kg * 8 + r * 4;
            int gm = bm + mm;
            float4 v = make_float4(0.f, 0.f, 0.f, 0.f);
            if (gm < NN) v = *(const float4*)&g_y[gm * 32 + k];
            As[k + 0][mm] = v.x; As[k + 1][mm] = v.y;
            As[k + 2][mm] = v.z; As[k + 3][mm] = v.w;
        }
    }
    {
        int id = tid * 4;
#pragma unroll
        for (int rep = 0; rep < 4; rep++, id += 1024) {
            int kk = id >> 7, col = id & 127;
            *(float4*)&Bs[kk][col] = *(const float4*)&gw[kk * 512 + bn + col];
        }
    }
    __syncthreads();
    float acc[4][8] = {};
#pragma unroll
    for (int kk = 0; kk < 32; kk++) {
        float a[4], bb[8];
#pragma unroll
        for (int i = 0; i < 4; i++) a[i] = As[kk][ty * 4 + i];
#pragma unroll
        for (int j = 0; j < 8; j++) bb[j] = Bs[kk][tx * 8 + j];
#pragma unroll
        for (int i = 0; i < 4; i++)
#pragma unroll
            for (int j = 0; j < 8; j++) acc[i][j] += a[i] * bb[j];
    }
    // store h tile
#pragma unroll
    for (int i = 0; i < 4; i++) {
        int gm = bm + ty * 4 + i;
        if (gm >= NN) continue;
#pragma unroll
        for (int j = 0; j < 8; j += 4) {
            float4 st = make_float4(acc[i][j], acc[i][j + 1], acc[i][j + 2], acc[i][j + 3]);
            *(float4*)&g_h[gm * 512 + bn + tx * 8 + j] = st;
        }
    }
    // fused attention partials over this 128-col slice
    float sa[8], da[8];
#pragma unroll
    for (int j = 0; j < 8; j++) {
        sa[j] = asrc[bn + tx * 8 + j];
        da[j] = adst[bn + tx * 8 + j];
    }
#pragma unroll
    for (int i = 0; i < 4; i++) {
        float pa = 0.f, pd = 0.f;
#pragma unroll
        for (int j = 0; j < 8; j++) { pa += acc[i][j] * sa[j]; pd += acc[i][j] * da[j]; }
#pragma unroll
        for (int off = 8; off; off >>= 1) {
            pa += __shfl_down_sync(0xffffffffu, pa, off, 16);
            pd += __shfl_down_sync(0xffffffffu, pd, off, 16);
        }
        int gm = bm + ty * 4 + i;
        if (tx == 0 && gm < NN) {
            atomicAdd(&g_asv[gm], pa);
            atomicAdd(&g_adv[gm], pd);
        }
    }
}

// ---------------- GAT per-node softmax + weighted sum ----------------
__global__ void gat_node_k() {
    __shared__ float sal[512];
    __shared__ int ssrc[512];
    __shared__ float red[128];
    int n = blockIdx.x, tid = threadIdx.x;
    int o = g_offs[n];
    int deg = g_offs[n + 1] - o;
    if (deg > 512) deg = 512;
    float advn = g_adv[n];
    float lm = -1e30f;
    for (int p = tid; p < deg; p += 128) {
        int s = g_csr[o + p] & 0xffff;
        ssrc[p] = s;
        float a = g_asv[s] + advn;
        a = a > 0.f ? a : 0.2f * a;
        sal[p] = a;
        lm = fmaxf(lm, a);
    }
    float als = g_asv[n] + advn;
    als = als > 0.f ? als : 0.2f * als;
    lm = fmaxf(lm, als);
    red[tid] = lm; __syncthreads();
    for (int st = 64; st; st >>= 1) {
        if (tid < st) red[tid] = fmaxf(red[tid], red[tid + st]);
        __syncthreads();
    }
    float m = red[0];
    __syncthreads();
    float ls = 0.f;
    for (int p = tid; p < deg; p += 128) {
        float ex = expf(sal[p] - m);
        sal[p] = ex;
        ls += ex;
    }
    float exs = expf(als - m);
    if (tid == 0) ls += exs;
    red[tid] = ls; __syncthreads();
    for (int st = 64; st; st >>= 1) {
        if (tid < st) red[tid] += red[tid + st];
        __syncthreads();
    }
    float invden = 1.f / fmaxf(red[0], 1e-16f);
    float cs = exs * invden;
    float4 hv = ((const float4*)&g_h[n * 512])[tid];
    float4 acc;
    acc.x = cs * hv.x; acc.y = cs * hv.y; acc.z = cs * hv.z; acc.w = cs * hv.w;
#pragma unroll 4
    for (int p = 0; p < deg; p++) {
        int s = ssrc[p];
        float c = sal[p] * invden;
        float4 h4 = ((const float4*)&g_h[s * 512])[tid];
        acc.x += c * h4.x; acc.y += c * h4.y; acc.z += c * h4.z; acc.w += c * h4.w;
    }
    ((float4*)&g_o512[n * 512])[tid] = acc;
}

// ---------------- AB GEMM: 128M x 128N tile, BK=16, 8x8/thread ----------------
__global__ void ab_gemm_k(const float* __restrict__ w1, const float* __restrict__ b1,
                          const float* __restrict__ gbias) {
    __shared__ float As[16][132];
    __shared__ float Bs[16][128];
    int tid = threadIdx.x;
    int bm = blockIdx.x * 128;
    int by = blockIdx.y;           // 0 -> g_A half (w1 rows 0..511), 1 -> g_B half
    int ty = tid >> 4, tx = tid & 15;
    float acc[8][8] = {};
    for (int k0 = 0; k0 < 512; k0 += 16) {
        {
            int mm = tid & 127, kg = (tid >> 7) * 8;
            int gm = bm + mm;
#pragma unroll
            for (int r = 0; r < 2; r++) {
                int k = kg + r * 4;
                float4 v = make_float4(0.f, 0.f, 0.f, 0.f);
                if (gm < NN) v = *(const float4*)&g_o512[gm * 512 + k0 + k];
                const float4 gb = *(const float4*)&gbias[k0 + k];
                As[k + 0][mm] = fmaxf(v.x + gb.x, 0.f);
                As[k + 1][mm] = fmaxf(v.y + gb.y, 0.f);
                As[k + 2][mm] = fmaxf(v.z + gb.z, 0.f);
                As[k + 3][mm] = fmaxf(v.w + gb.w, 0.f);
            }
        }
        {
            int kk = tid >> 4, col = (tid & 15) * 8;
            const float* wrow = &w1[(k0 + kk + by * 512) * 128];
            *(float4*)&Bs[kk][col] = *(const float4*)&wrow[col];
            *(float4*)&Bs[kk][col + 4] = *(const float4*)&wrow[col + 4];
        }
        __syncthreads();
#pragma unroll
        for (int kk = 0; kk < 16; kk++) {
            float a[8], bb[8];
#pragma unroll
            for (int i = 0; i < 8; i++) a[i] = As[kk][ty * 8 + i];
#pragma unroll
            for (int j = 0; j < 8; j++) bb[j] = Bs[kk][tx * 8 + j];
#pragma unroll
            for (int i = 0; i < 8; i++)
#pragma unroll
                for (int j = 0; j < 8; j++) acc[i][j] += a[i] * bb[j];
        }
        __syncthreads();
    }
#pragma unroll
    for (int i = 0; i < 8; i++) {
        int gm = bm + ty * 8 + i;
        if (gm >= NN) continue;
#pragma unroll
        for (int j = 0; j < 8; j++) {
            int c = tx * 8 + j;
            float v = acc[i][j];
            if (by == 0) v += b1[c];
            if (by == 0) g_A[gm * 128 + c] = v;
            else         g_B[gm * 128 + c] = v;
        }
    }
}

__global__ void final_k(const int* __restrict__ src, const int* __restrict__ dst,
                        const float* __restrict__ w2, const float* __restrict__ b2,
                        float* __restrict__ out) {
    int e = blockIdx.x * 4 + (threadIdx.x >> 5);
    int lane = threadIdx.x & 31;
    if (e >= EE) return;
    int s = src[e], d = dst[e];
    float4 a = *(const float4*)&g_A[s * 128 + lane * 4];
    float4 b = *(const float4*)&g_B[d * 128 + lane * 4];
    float4 w = *(const float4*)&w2[lane * 4];
    float sum = fmaxf(a.x + b.x, 0.f) * w.x + fmaxf(a.y + b.y, 0.f) * w.y +
                fmaxf(a.z + b.z, 0.f) * w.z + fmaxf(a.w + b.w, 0.f) * w.w;
#pragma unroll
    for (int off = 16; off; off >>= 1) sum += __shfl_down_sync(0xffffffffu, sum, off);
    if (lane == 0) out[e] = 1.f / (1.f + expf(-(sum + b2[0])));
}

// ---------------- host ----------------
extern "C" void kernel_launch(void* const* d_in, const int* in_sizes, int n_in,
                              void* d_out, int out_size) {
    int b = (in_sizes[0] == 2 * EE) ? 2 : 0;
    const int* eidx = (const int*)(b ? d_in[0] : d_in[24]);
    const int* etype = (const int*)(b ? d_in[1] : d_in[25]);
    const int* src = eidx;
    const int* dst = eidx + EE;
    auto F = [&](int i) { return (const float*)d_in[i]; };

    // CSR build
    zero_k<<<(2 * NN + 255) / 256, 256>>>();
    count_k<<<(EE + 255) / 256, 256>>>(etype, dst);
    scan_k<<<1, 1024>>>();
    scatter_k<<<(EE + 255) / 256, 256>>>(src, dst, etype);

    // fused precompute
    int ptot = R0 + 4096 + 8192 + 4096;
    precomp_k<<<(ptot + 255) / 256, 256>>>(F(b + 0), F(b + 1), F(b + 4), F(b + 5),
                                           F(b + 8), F(b + 9), F(b + 12), F(b + 13));
    // layer 0
    l0_agg_k<<<NN / 4, 128>>>(F(b + 2), F(b + 3));

    // fused layers 1..3 (L1 x->y, L2 y->x, L3 x->y)
    dim3 blk(64, 4);
    layer_k<<<NN / 4, blk>>>(F(b + 6),  F(b + 7),  1, 32, 64, 0);
    layer_k<<<NN / 4, blk>>>(F(b + 10), F(b + 11), 2, 64, 64, 1);
    layer_k<<<NN / 4, blk>>>(F(b + 14), F(b + 15), 3, 64, 32, 0);

    // GAT (attn fused into gemm epilogue)
    dim3 hg((NN + 63) / 64, 4);
    gath_gemm_k<<<hg, 256>>>(F(b + 16), F(b + 17), F(b + 18));
    gat_node_k<<<NN, 128>>>();

    // edge MLP
    dim3 abgrid((NN + 127) / 128, 2);
    ab_gemm_k<<<abgrid, 256>>>(F(b + 20), F(b + 21), F(b + 19));
    final_k<<<(EE + 3) / 4, 128>>>(src, dst, F(b + 22), F(b + 23), (float*)d_out);
}

// round 10
// speedup vs baseline: 3.3666x; 1.0244x over previous
#include <cuda_runtime.h>
#include <cuda_bf16.h>
#include <math.h>

#define NN 6000
#define EE 100000

// ---------------- scratch (device-only; NEVER passed from host) ----------------
__device__ float g_x[NN * 64];          // ping
__device__ float g_y[NN * 64];          // pong
__device__ float g_hr[2 * NN * 32];     // layer0 relation rows
__device__ float g_W1[32 * 128];        // [I, 2*O]
__device__ float g_W2[64 * 128];
__device__ float g_W3[64 * 64];
__device__ int   g_cnt[2 * NN];
__device__ float g_rinv[2 * NN];
__device__ int   g_offs[NN + 1];
__device__ int   g_cur[NN];
__device__ int   g_csr[EE];             // src | (rel<<16)
__device__ float g_h[NN * 512];
__device__ float g_asv[NN], g_adv[NN];
__device__ float g_o512[NN * 512];
__device__ float g_A[NN * 128], g_B[NN * 128];

// ---------------- CSR build ----------------
__global__ void zero_k() {
    int i = blockIdx.x * blockDim.x + threadIdx.x;
    if (i < 2 * NN) g_cnt[i] = 0;
    if (i < NN) { g_cur[i] = 0; g_asv[i] = 0.f; g_adv[i] = 0.f; }
}
__global__ void count_k(const int* __restrict__ et, const int* __restrict__ dst) {
    int e = blockIdx.x * blockDim.x + threadIdx.x;
    if (e < EE) atomicAdd(&g_cnt[et[e] * NN + dst[e]], 1);
}
// scan of deg (=cnt0+cnt1) + rinv, single block 1024 threads
__global__ void scan_k() {
    __shared__ int ws[32];
    int t = threadIdx.x;
    for (int i = t; i < 2 * NN; i += 1024)
        g_rinv[i] = 1.0f / fmaxf((float)g_cnt[i], 1.0f);
    int base = t * 6;
    int loc[6]; int s = 0;
#pragma unroll
    for (int j = 0; j < 6; j++) {
        int idx = base + j; loc[j] = s;
        s += (idx < NN) ? (g_cnt[idx] + g_cnt[NN + idx]) : 0;
    }
    int lane = t & 31, w = t >> 5;
    int v = s;
#pragma unroll
    for (int off = 1; off < 32; off <<= 1) {
        int nv = __shfl_up_sync(0xffffffffu, v, off);
        if (lane >= off) v += nv;
    }
    if (lane == 31) ws[w] = v;
    __syncthreads();
    if (w == 0) {
        int x = ws[lane];
#pragma unroll
        for (int off = 1; off < 32; off <<= 1) {
            int nv = __shfl_up_sync(0xffffffffu, x, off);
            if (lane >= off) x += nv;
        }
        ws[lane] = x;
    }
    __syncthreads();
    int excl = v - s + (w ? ws[w - 1] : 0);
#pragma unroll
    for (int j = 0; j < 6; j++) {
        int idx = base + j;
        if (idx < NN) g_offs[idx] = excl + loc[j];
    }
    if (t == 1023) g_offs[NN] = excl + s;
}
__global__ void scatter_k(const int* __restrict__ src, const int* __restrict__ dst,
                          const int* __restrict__ et) {
    int e = blockIdx.x * blockDim.x + threadIdx.x;
    if (e >= EE) return;
    int d = dst[e];
    int pos = g_offs[d] + atomicAdd(&g_cur[d], 1);
    g_csr[pos] = src[e] | (et[e] << 16);
}

// ---------------- fused precompute: l0_hr + Wcat 1..3 ----------------
__device__ __forceinline__ void wcat_one(float* W, const float* basis, const float* comp,
                                         int I, int O, int i) {
    int r = i / (I * O), io = i % (I * O);
    float acc = 0.f;
#pragma unroll
    for (int b = 0; b < 4; b++) acc += comp[r * 4 + b] * basis[b * I * O + io];
    W[(io / O) * 2 * O + r * O + (io % O)] = acc;
}
#define R0 (2 * NN * 32)
__global__ void precomp_k(const float* __restrict__ basis0, const float* __restrict__ comp0,
                          const float* __restrict__ b1s, const float* __restrict__ c1,
                          const float* __restrict__ b2s, const float* __restrict__ c2,
                          const float* __restrict__ b3s, const float* __restrict__ c3) {
    int i = blockIdx.x * blockDim.x + threadIdx.x;
    if (i < R0) {
        int r = i / (NN * 32), idx = i % (NN * 32);
        float acc = 0.f;
#pragma unroll
        for (int b = 0; b < 4; b++) acc += comp0[r * 4 + b] * basis0[b * NN * 32 + idx];
        g_hr[r * NN * 32 + idx] = acc;
    } else if (i < R0 + 4096) {
        wcat_one(g_W1, b1s, c1, 32, 64, i - R0);
    } else if (i < R0 + 4096 + 8192) {
        wcat_one(g_W2, b2s, c2, 64, 64, i - R0 - 4096);
    } else if (i < R0 + 4096 + 8192 + 4096) {
        wcat_one(g_W3, b3s, c3, 64, 32, i - R0 - 4096 - 8192);
    }
}

// ---------------- layer 0: gather + root + bias + tanh ----------------
__global__ void l0_agg_k(const float* __restrict__ root0, const float* __restrict__ rbias0) {
    int n = blockIdx.x * 4 + (threadIdx.x >> 5);
    int lane = threadIdx.x & 31;
    if (n >= NN) return;
    int o = g_offs[n], e2 = g_offs[n + 1];
    float a0 = 0.f, a1 = 0.f;
    for (int p = o; p < e2; p++) {
        int pk = g_csr[p];
        float v = g_hr[(pk >> 16) * NN * 32 + (pk & 0xffff) * 32 + lane];
        if (pk & 0x10000) a1 += v; else a0 += v;
    }
    float out = root0[n * 32 + lane] + rbias0[lane] + a0 * g_rinv[n] + a1 * g_rinv[NN + n];
    g_x[n * 32 + lane] = tanhf(out);
}

// ---------------- fused RGCN layer: aggregate + GEMM + tanh ----------------
__global__ void layer_k(const float* __restrict__ root, const float* __restrict__ rbias,
                        int layer, int I, int O, int inflag) {
    __shared__ float xs[4][64], a0s[4][64], a1s[4][64];
    const float* xin = inflag ? g_y : g_x;
    float* xout = inflag ? g_x : g_y;
    const float* Wcat = (layer == 1) ? g_W1 : (layer == 2) ? g_W2 : g_W3;
    int ty = threadIdx.y, tx = threadIdx.x;
    int n = blockIdx.x * 4 + ty;
    if (tx < I) {
        int o = g_offs[n], e2 = g_offs[n + 1];
        float a0 = 0.f, a1 = 0.f;
#pragma unroll 4
        for (int p = o; p < e2; p++) {
            int pk = g_csr[p];
            float v = xin[(pk & 0xffff) * I + tx];
            if (pk & 0x10000) a1 += v; else a0 += v;
        }
        xs[ty][tx] = xin[n * I + tx];
        a0s[ty][tx] = a0 * g_rinv[n];
        a1s[ty][tx] = a1 * g_rinv[NN + n];
    }
    __syncthreads();
    if (tx < O) {
        float acc = rbias[tx];
#pragma unroll 8
        for (int i = 0; i < I; i++) {
            acc += xs[ty][i] * root[i * O + tx];
            acc += a0s[ty][i] * Wcat[i * 2 * O + tx];
            acc += a1s[ty][i] * Wcat[i * 2 * O + O + tx];
        }
        xout[n * O + tx] = tanhf(acc);
    }
}

// ---------------- GAT h GEMM + fused attention partials ----------------
__global__ void gath_gemm_k(const float* __restrict__ gw, const float* __restrict__ asrc,
                            const float* __restrict__ adst) {
    __shared__ float As[32][68];
    __shared__ float Bs[32][128];
    int tid = threadIdx.x;
    int bm = blockIdx.x * 64, bn = blockIdx.y * 128;
    int ty = tid >> 4, tx = tid & 15;
    {
        int mm = tid & 63, kg = tid >> 6;
#pragma unroll
        for (int r = 0; r < 2; r++) {
            int k = kg * 8 + r * 4;
            int gm = bm + mm;
            float4 v = make_float4(0.f, 0.f, 0.f, 0.f);
            if (gm < NN) v = *(const float4*)&g_y[gm * 32 + k];
            As[k + 0][mm] = v.x; As[k + 1][mm] = v.y;
            As[k + 2][mm] = v.z; As[k + 3][mm] = v.w;
        }
    }
    {
        int id = tid * 4;
#pragma unroll
        for (int rep = 0; rep < 4; rep++, id += 1024) {
            int kk = id >> 7, col = id & 127;
            *(float4*)&Bs[kk][col] = *(const float4*)&gw[kk * 512 + bn + col];
        }
    }
    __syncthreads();
    float acc[4][8] = {};
#pragma unroll
    for (int kk = 0; kk < 32; kk++) {
        float a[4], bb[8];
#pragma unroll
        for (int i = 0; i < 4; i++) a[i] = As[kk][ty * 4 + i];
#pragma unroll
        for (int j = 0; j < 8; j++) bb[j] = Bs[kk][tx * 8 + j];
#pragma unroll
        for (int i = 0; i < 4; i++)
#pragma unroll
            for (int j = 0; j < 8; j++) acc[i][j] += a[i] * bb[j];
    }
#pragma unroll
    for (int i = 0; i < 4; i++) {
        int gm = bm + ty * 4 + i;
        if (gm >= NN) continue;
#pragma unroll
        for (int j = 0; j < 8; j += 4) {
            float4 st = make_float4(acc[i][j], acc[i][j + 1], acc[i][j + 2], acc[i][j + 3]);
            *(float4*)&g_h[gm * 512 + bn + tx * 8 + j] = st;
        }
    }
    float sa[8], da[8];
#pragma unroll
    for (int j = 0; j < 8; j++) {
        sa[j] = asrc[bn + tx * 8 + j];
        da[j] = adst[bn + tx * 8 + j];
    }
#pragma unroll
    for (int i = 0; i < 4; i++) {
        float pa = 0.f, pd = 0.f;
#pragma unroll
        for (int j = 0; j < 8; j++) { pa += acc[i][j] * sa[j]; pd += acc[i][j] * da[j]; }
#pragma unroll
        for (int off = 8; off; off >>= 1) {
            pa += __shfl_down_sync(0xffffffffu, pa, off, 16);
            pd += __shfl_down_sync(0xffffffffu, pd, off, 16);
        }
        int gm = bm + ty * 4 + i;
        if (tx == 0 && gm < NN) {
            atomicAdd(&g_asv[gm], pa);
            atomicAdd(&g_adv[gm], pd);
        }
    }
}

// ---------------- GAT softmax + weighted sum: 4 nodes / 128-thread block ----------------
// warp per node; shfl-only reductions; aggregation warp-owned (32 lanes x float4 x 4 chunks).
__global__ void gat_node_k() {
    __shared__ float sal[4][512];
    __shared__ int ssrc[4][512];
    int wid = threadIdx.x >> 5, lane = threadIdx.x & 31;
    int n = blockIdx.x * 4 + wid;
    if (n >= NN) return;
    int o = g_offs[n];
    int deg = g_offs[n + 1] - o;
    if (deg > 512) deg = 512;
    float advn = g_adv[n];
    float* wsal = sal[wid];
    int* wsrc = ssrc[wid];
    float lm = -1e30f;
    for (int p = lane; p < deg; p += 32) {
        int s = g_csr[o + p] & 0xffff;
        wsrc[p] = s;
        float a = g_asv[s] + advn;
        a = a > 0.f ? a : 0.2f * a;
        wsal[p] = a;
        lm = fmaxf(lm, a);
    }
    float als = g_asv[n] + advn;
    als = als > 0.f ? als : 0.2f * als;
    lm = fmaxf(lm, als);
#pragma unroll
    for (int off = 16; off; off >>= 1)
        lm = fmaxf(lm, __shfl_xor_sync(0xffffffffu, lm, off));
    float m = lm;
    float ls = 0.f;
    __syncwarp();
    for (int p = lane; p < deg; p += 32) {
        float ex = expf(wsal[p] - m);
        wsal[p] = ex;
        ls += ex;
    }
    float exs = expf(als - m);
    if (lane == 0) ls += exs;
#pragma unroll
    for (int off = 16; off; off >>= 1)
        ls += __shfl_xor_sync(0xffffffffu, ls, off);
    float invden = 1.f / fmaxf(ls, 1e-16f);
    float cs = exs * invden;
    __syncwarp();
    // aggregation: 4 col-chunks of 128 floats (lane owns float4 per chunk)
#pragma unroll
    for (int q = 0; q < 4; q++) {
        int cidx = q * 32 + lane;
        float4 hv = ((const float4*)&g_h[n * 512])[cidx];
        float4 acc;
        acc.x = cs * hv.x; acc.y = cs * hv.y; acc.z = cs * hv.z; acc.w = cs * hv.w;
        for (int p = 0; p < deg; p++) {
            int s = wsrc[p];
            float c = wsal[p] * invden;
            float4 h4 = ((const float4*)&g_h[s * 512])[cidx];
            acc.x += c * h4.x; acc.y += c * h4.y; acc.z += c * h4.z; acc.w += c * h4.w;
        }
        ((float4*)&g_o512[n * 512])[cidx] = acc;
    }
}

// ---------------- AB GEMM: 64M x 128N tile, BK=16, 8x8/thread, 128 threads ----------------
__global__ void ab_gemm_k(const float* __restrict__ w1, const float* __restrict__ b1,
                          const float* __restrict__ gbias) {
    __shared__ float As[16][68];
    __shared__ float Bs[16][128];
    int tid = threadIdx.x;               // 128
    int bm = blockIdx.x * 64;
    int by = blockIdx.y;                 // 0 -> g_A half, 1 -> g_B half
    int ty = tid >> 4, tx = tid & 15;    // ty 0..7, tx 0..15
    float acc[8][8] = {};
    for (int k0 = 0; k0 < 512; k0 += 16) {
        {
            int mm = tid & 63, kg = tid >> 6;    // kg 0..1, each covers 8 k's
            int gm = bm + mm;
#pragma unroll
            for (int r = 0; r < 2; r++) {
                int k = kg * 8 + r * 4;
                float4 v = make_float4(0.f, 0.f, 0.f, 0.f);
                if (gm < NN) v = *(const float4*)&g_o512[gm * 512 + k0 + k];
                const float4 gb = *(const float4*)&gbias[k0 + k];
                As[k + 0][mm] = fmaxf(v.x + gb.x, 0.f);
                As[k + 1][mm] = fmaxf(v.y + gb.y, 0.f);
                As[k + 2][mm] = fmaxf(v.z + gb.z, 0.f);
                As[k + 3][mm] = fmaxf(v.w + gb.w, 0.f);
            }
        }
        {
            int id = tid * 4;
#pragma unroll
            for (int rep = 0; rep < 4; rep++, id += 512) {
                int kk = id >> 7, col = id & 127;
                *(float4*)&Bs[kk][col] = *(const float4*)&w1[(k0 + kk + by * 512) * 128 + col];
            }
        }
        __syncthreads();
#pragma unroll
        for (int kk = 0; kk < 16; kk++) {
            float a[8], bb[8];
#pragma unroll
            for (int i = 0; i < 8; i++) a[i] = As[kk][((ty & 3) * 8 + i) + (ty >> 2) * 32];
#pragma unroll
            for (int j = 0; j < 8; j++) bb[j] = Bs[kk][tx * 8 + j];
#pragma unroll
            for (int i = 0; i < 8; i++)
#pragma unroll
                for (int j = 0; j < 8; j++) acc[i][j] += a[i] * bb[j];
        }
        __syncthreads();
    }
#pragma unroll
    for (int i = 0; i < 8; i++) {
        int gm = bm + ((ty & 3) * 8 + i) + (ty >> 2) * 32;
        if (gm >= NN) continue;
#pragma unroll
        for (int j = 0; j < 8; j++) {
            int c = tx * 8 + j;
            float v = acc[i][j];
            if (by == 0) v += b1[c];
            if (by == 0) g_A[gm * 128 + c] = v;
            else         g_B[gm * 128 + c] = v;
        }
    }
}

__global__ void final_k(const int* __restrict__ src, const int* __restrict__ dst,
                        const float* __restrict__ w2, const float* __restrict__ b2,
                        float* __restrict__ out) {
    int e = blockIdx.x * 4 + (threadIdx.x >> 5);
    int lane = threadIdx.x & 31;
    if (e >= EE) return;
    int s = src[e], d = dst[e];
    float4 a = *(const float4*)&g_A[s * 128 + lane * 4];
    float4 b = *(const float4*)&g_B[d * 128 + lane * 4];
    float4 w = *(const float4*)&w2[lane * 4];
    float sum = fmaxf(a.x + b.x, 0.f) * w.x + fmaxf(a.y + b.y, 0.f) * w.y +
                fmaxf(a.z + b.z, 0.f) * w.z + fmaxf(a.w + b.w, 0.f) * w.w;
#pragma unroll
    for (int off = 16; off; off >>= 1) sum += __shfl_down_sync(0xffffffffu, sum, off);
    if (lane == 0) out[e] = 1.f / (1.f + expf(-(sum + b2[0])));
}

// ---------------- host ----------------
extern "C" void kernel_launch(void* const* d_in, const int* in_sizes, int n_in,
                              void* d_out, int out_size) {
    int b = (in_sizes[0] == 2 * EE) ? 2 : 0;
    const int* eidx = (const int*)(b ? d_in[0] : d_in[24]);
    const int* etype = (const int*)(b ? d_in[1] : d_in[25]);
    const int* src = eidx;
    const int* dst = eidx + EE;
    auto F = [&](int i) { return (const float*)d_in[i]; };

    // CSR build
    zero_k<<<(2 * NN + 255) / 256, 256>>>();
    count_k<<<(EE + 255) / 256, 256>>>(etype, dst);
    scan_k<<<1, 1024>>>();
    scatter_k<<<(EE + 255) / 256, 256>>>(src, dst, etype);

    // fused precompute
    int ptot = R0 + 4096 + 8192 + 4096;
    precomp_k<<<(ptot + 255) / 256, 256>>>(F(b + 0), F(b + 1), F(b + 4), F(b + 5),
                                           F(b + 8), F(b + 9), F(b + 12), F(b + 13));
    // layer 0
    l0_agg_k<<<NN / 4, 128>>>(F(b + 2), F(b + 3));

    // fused layers 1..3 (L1 x->y, L2 y->x, L3 x->y)
    dim3 blk(64, 4);
    layer_k<<<NN / 4, blk>>>(F(b + 6),  F(b + 7),  1, 32, 64, 0);
    layer_k<<<NN / 4, blk>>>(F(b + 10), F(b + 11), 2, 64, 64, 1);
    layer_k<<<NN / 4, blk>>>(F(b + 14), F(b + 15), 3, 64, 32, 0);

    // GAT (attn fused into gemm epilogue)
    dim3 hg((NN + 63) / 64, 4);
    gath_gemm_k<<<hg, 256>>>(F(b + 16), F(b + 17), F(b + 18));
    gat_node_k<<<(NN + 3) / 4, 128>>>();

    // edge MLP
    dim3 abgrid((NN + 63) / 64, 2);
    ab_gemm_k<<<abgrid, 128>>>(F(b + 20), F(b + 21), F(b + 19));
    final_k<<<(EE + 3) / 4, 128>>>(src, dst, F(b + 22), F(b + 23), (float*)d_out);
}